// round 4
// baseline (speedup 1.0000x reference)
#include <cuda_runtime.h>
#include <math.h>

#define BB  2
#define C   64
#define H   256
#define W   256
#define HW  (H*W)
#define KK  9
#define DG  8
#define CG  8
#define CIN 128
#define NOFF 144
#define NMSK 72
#define NOC  216   // 144 offset + 72 mask channels

// Scratch for raw conv outputs: [b][ch(216)][y][x]
__device__ float g_scr[BB * NOC * H * W];

// ---------------------------------------------------------------------------
// Kernel A: fused offset+mask 3x3 conv over concat(ref, neighbour) (128 ch in)
// Block tile: 16x8 pixels, 32 out channels. 256 threads.
// Thread tile: 2 px x 8 oc (16 accumulators).
// ---------------------------------------------------------------------------
#define TX 16
#define TY 8
#define OCT 32
#define ICC 8
#define OCB_COUNT 7   // ceil(216/32)

__global__ __launch_bounds__(256) void convA(const float* __restrict__ ref,
                                             const float* __restrict__ nbr,
                                             const float* __restrict__ off_w,
                                             const float* __restrict__ off_b,
                                             const float* __restrict__ mask_w,
                                             const float* __restrict__ mask_b)
{
    __shared__ float sIn[ICC][TY+2][TX+4];   // [8][10][20] (padded row)
    __shared__ float sW[ICC*9][36];          // [72][36] (padded for banks, 16B-aligned rows)

    const int bx  = blockIdx.x;          // W/16
    const int by  = blockIdx.y;          // H/8
    const int bz  = blockIdx.z;          // b*7 + ocb
    const int b   = bz / OCB_COUNT;
    const int ocb = bz % OCB_COUNT;

    const int tid  = threadIdx.x;
    const int oc_t = tid & 3;            // 4 oc-groups of 8
    const int px_t = tid >> 2;           // 64 px-threads, each owns 2 px
    const int p0y  = px_t >> 4;          // 0..3 (second px at +4 rows)
    const int p0x  = px_t & 15;
    const int x0 = bx * TX, y0 = by * TY;

    float acc[2][8];
#pragma unroll
    for (int i = 0; i < 2; i++)
#pragma unroll
        for (int j = 0; j < 8; j++) acc[i][j] = 0.f;

    const float* in0 = ref + (size_t)b * C * HW;
    const float* in1 = nbr + (size_t)b * C * HW;

    for (int ch = 0; ch < CIN; ch += ICC) {
        // ---- load input patch [8][10][18] (zero-padded borders) ----
        for (int idx = tid; idx < ICC * (TY+2) * (TX+2); idx += 256) {
            int icl = idx / ((TY+2)*(TX+2));
            int r   = idx % ((TY+2)*(TX+2));
            int py  = r / (TX+2);
            int px  = r % (TX+2);
            int gy = y0 - 1 + py;
            int gx = x0 - 1 + px;
            int ic = ch + icl;
            float v = 0.f;
            if (gy >= 0 && gy < H && gx >= 0 && gx < W) {
                const float* src = (ic < C) ? (in0 + (size_t)ic * HW)
                                            : (in1 + (size_t)(ic - C) * HW);
                v = src[gy * W + gx];
            }
            sIn[icl][py][px] = v;
        }
        // ---- load weights: sW[ks][oc] = w[ocg][ch+icl][kk], ks=icl*9+kk ----
        for (int idx = tid; idx < OCT * 72; idx += 256) {
            int oc = idx / 72;
            int ks = idx % 72;           // consecutive ks -> contiguous global
            int ocg = ocb * OCT + oc;
            float v = 0.f;
            if (ocg < NOFF)      v = off_w [(size_t)ocg * CIN * 9 + (size_t)ch * 9 + ks];
            else if (ocg < NOC)  v = mask_w[(size_t)(ocg - NOFF) * CIN * 9 + (size_t)ch * 9 + ks];
            sW[ks][oc] = v;
        }
        __syncthreads();

        for (int icl = 0; icl < ICC; icl++) {
#pragma unroll
            for (int kk = 0; kk < 9; kk++) {
                const int ki = kk / 3, kj = kk % 3;
                float a0 = sIn[icl][p0y + ki][p0x + kj];
                float a1 = sIn[icl][p0y + 4 + ki][p0x + kj];
                const float4* wp = reinterpret_cast<const float4*>(&sW[icl*9 + kk][oc_t*8]);
                float4 wA = wp[0], wB = wp[1];
                acc[0][0] += a0 * wA.x; acc[0][1] += a0 * wA.y;
                acc[0][2] += a0 * wA.z; acc[0][3] += a0 * wA.w;
                acc[0][4] += a0 * wB.x; acc[0][5] += a0 * wB.y;
                acc[0][6] += a0 * wB.z; acc[0][7] += a0 * wB.w;
                acc[1][0] += a1 * wA.x; acc[1][1] += a1 * wA.y;
                acc[1][2] += a1 * wA.z; acc[1][3] += a1 * wA.w;
                acc[1][4] += a1 * wB.x; acc[1][5] += a1 * wB.y;
                acc[1][6] += a1 * wB.z; acc[1][7] += a1 * wB.w;
            }
        }
        __syncthreads();
    }

    // ---- store (+bias) ----
#pragma unroll
    for (int i = 0; i < 2; i++) {
        int gy = y0 + p0y + i * 4;
        int gx = x0 + p0x;
#pragma unroll
        for (int j = 0; j < 8; j++) {
            int ocg = ocb * OCT + oc_t * 8 + j;
            if (ocg < NOC) {
                float bv = (ocg < NOFF) ? off_b[ocg] : mask_b[ocg - NOFF];
                g_scr[((size_t)(b * NOC + ocg) * H + gy) * W + gx] = acc[i][j] + bv;
            }
        }
    }
}

// ---------------------------------------------------------------------------
// Kernel B: deformable bilinear sampling * sigmoid(mask) -> smem,
// then GEMM vs weight (K=576) + bias.
// Block: 16 pixels of one row; 128 threads.
// ---------------------------------------------------------------------------
#define TPX 16
#define KTOT 576
#define ASTR 577   // padded stride (odd -> conflict-free px access)
#define KC 32

__global__ __launch_bounds__(128) void kernB(const float* __restrict__ nbr,
                                             const float* __restrict__ weight,
                                             const float* __restrict__ bias,
                                             float* __restrict__ out)
{
    __shared__ float sA[TPX * ASTR];     // 36928 B
    __shared__ float sWt[KC][68];        // 8704 B (padded)

    const int bx = blockIdx.x;           // W/16
    const int y  = blockIdx.y;           // H
    const int b  = blockIdx.z;           // B
    const int x0 = bx * TPX;
    const int tid = threadIdx.x;

    const float* scr = g_scr + (size_t)b * NOC * HW;
    const float* img = nbr   + (size_t)b * C * HW;

    // ---- phase 1: sampled * mask into sA[p][(g*8+c)*9 + k] ----
    for (int task = tid; task < TPX * 72; task += 128) {
        int p  = task / 72;
        int gk = task - p * 72;
        int g  = gk / 9;
        int k  = gk - g * 9;
        int x  = x0 + p;
        int base = y * W + x;

        float dy = scr[(size_t)(2*gk)     * HW + base];
        float dx = scr[(size_t)(2*gk + 1) * HW + base];
        float mr = scr[(size_t)(NOFF + gk) * HW + base];
        float m  = 1.f / (1.f + expf(-mr));

        float ys = dy + (float)(y - 1 + k / 3);
        float xs = dx + (float)(x - 1 + k % 3);
        float yf = floorf(ys), xf = floorf(xs);
        float wy = ys - yf,    wx = xs - xf;
        int yi = (int)yf, xi = (int)xf;

        bool vy0 = (yi >= 0) && (yi < H);
        bool vy1 = (yi + 1 >= 0) && (yi + 1 < H);
        bool vx0 = (xi >= 0) && (xi < W);
        bool vx1 = (xi + 1 >= 0) && (xi + 1 < W);

        float w00 = ((vy0 && vx0) ? (1.f - wy) * (1.f - wx) : 0.f) * m;
        float w01 = ((vy0 && vx1) ? (1.f - wy) * wx         : 0.f) * m;
        float w10 = ((vy1 && vx0) ? wy * (1.f - wx)         : 0.f) * m;
        float w11 = ((vy1 && vx1) ? wy * wx                 : 0.f) * m;

        int yc0 = min(max(yi,     0), H - 1);
        int yc1 = min(max(yi + 1, 0), H - 1);
        int xc0 = min(max(xi,     0), W - 1);
        int xc1 = min(max(xi + 1, 0), W - 1);

        int o00 = yc0 * W + xc0, o01 = yc0 * W + xc1;
        int o10 = yc1 * W + xc0, o11 = yc1 * W + xc1;

        const float* cbase = img + (size_t)(g * CG) * HW;
        float* dst = &sA[p * ASTR + (g * CG) * 9 + k];
#pragma unroll
        for (int c = 0; c < CG; c++) {
            const float* pc = cbase + (size_t)c * HW;
            float v = w00 * __ldg(pc + o00) + w01 * __ldg(pc + o01)
                    + w10 * __ldg(pc + o10) + w11 * __ldg(pc + o11);
            dst[c * 9] = v;
        }
    }
    __syncthreads();

    // ---- phase 2: out[p][o] = sum_k sA[p][k] * weight[o][k] ----
    const int oc_t = tid & 15;   // 16 groups x 4 oc
    const int px_t = tid >> 4;   // 8 -> handles px_t and px_t+8
    float acc[2][4];
#pragma unroll
    for (int i = 0; i < 2; i++)
#pragma unroll
        for (int j = 0; j < 4; j++) acc[i][j] = 0.f;

    for (int k0 = 0; k0 < KTOT; k0 += KC) {
        for (int idx = tid; idx < KC * 64; idx += 128) {
            int o  = idx / KC;
            int kl = idx % KC;           // consecutive kl -> contiguous global
            sWt[kl][o] = weight[(size_t)o * KTOT + k0 + kl];
        }
        __syncthreads();
#pragma unroll 8
        for (int kl = 0; kl < KC; kl++) {
            float a0 = sA[px_t * ASTR + k0 + kl];
            float a1 = sA[(px_t + 8) * ASTR + k0 + kl];
            float4 wv = *reinterpret_cast<const float4*>(&sWt[kl][oc_t * 4]);
            acc[0][0] += a0 * wv.x; acc[0][1] += a0 * wv.y;
            acc[0][2] += a0 * wv.z; acc[0][3] += a0 * wv.w;
            acc[1][0] += a1 * wv.x; acc[1][1] += a1 * wv.y;
            acc[1][2] += a1 * wv.z; acc[1][3] += a1 * wv.w;
        }
        __syncthreads();
    }

    // ---- store + bias ----
#pragma unroll
    for (int i = 0; i < 2; i++) {
        int p = px_t + i * 8;
        int x = x0 + p;
#pragma unroll
        for (int j = 0; j < 4; j++) {
            int o = oc_t * 4 + j;
            out[((size_t)(b * C + o) * H + y) * W + x] = acc[i][j] + bias[o];
        }
    }
}

// ---------------------------------------------------------------------------
extern "C" void kernel_launch(void* const* d_in, const int* in_sizes, int n_in,
                              void* d_out, int out_size) {
    const float* ref    = (const float*)d_in[0];
    const float* nbr    = (const float*)d_in[1];
    const float* off_w  = (const float*)d_in[2];
    const float* off_b  = (const float*)d_in[3];
    const float* mask_w = (const float*)d_in[4];
    const float* mask_b = (const float*)d_in[5];
    const float* weight = (const float*)d_in[6];
    const float* bias   = (const float*)d_in[7];
    float* out = (float*)d_out;

    dim3 gA(W / TX, H / TY, BB * OCB_COUNT);
    convA<<<gA, 256>>>(ref, nbr, off_w, off_b, mask_w, mask_b);

    dim3 gB(W / TPX, H, BB);
    kernB<<<gB, 128>>>(nbr, weight, bias, out);
}

// round 5
// speedup vs baseline: 1.1575x; 1.1575x over previous
#include <cuda_runtime.h>
#include <math.h>
#include <stdint.h>

#define BB  2
#define C   64
#define H   256
#define W   256
#define HW  (H*W)
#define KK  9
#define DG  8
#define CG  8
#define CIN 128
#define NOFF 144
#define NMSK 72
#define NOC  216   // 144 offset + 72 mask channels

// Packed fp32x2 FMA (Blackwell): 2 fp32 MACs per FMA-pipe slot.
#define FMA_F32X2(acc, a, b) \
    asm("fma.rn.f32x2 %0, %1, %2, %0;" : "+l"(acc) : "l"(a), "l"(b))
#define PACK2(out, lo, hi) \
    asm("mov.b64 %0, {%1, %2};" : "=l"(out) : "f"(lo), "f"(hi))

// Scratch for raw conv outputs: [b][ch(216)][y][x]
__device__ float g_scr[BB * NOC * H * W];

// ---------------------------------------------------------------------------
// Kernel A: fused offset+mask 3x3 conv over concat(ref, neighbour) (128 ch in)
// Block tile: 16x8 pixels, 32 out channels. 256 threads.
// Thread tile: 2 px x 8 oc (as 2x4 f32x2 accumulators).
// ---------------------------------------------------------------------------
#define TX 16
#define TY 8
#define OCT 32
#define ICC 8
#define OCB_COUNT 7   // ceil(216/32)

__global__ __launch_bounds__(256) void convA(const float* __restrict__ ref,
                                             const float* __restrict__ nbr,
                                             const float* __restrict__ off_w,
                                             const float* __restrict__ off_b,
                                             const float* __restrict__ mask_w,
                                             const float* __restrict__ mask_b)
{
    __shared__ __align__(16) float sIn[ICC][TY+2][TX+4];   // [8][10][20]
    __shared__ __align__(16) float sW[ICC*9][36];          // rows 144B (16B mult)

    const int bx  = blockIdx.x;          // W/16
    const int by  = blockIdx.y;          // H/8
    const int bz  = blockIdx.z;          // b*7 + ocb
    const int b   = bz / OCB_COUNT;
    const int ocb = bz % OCB_COUNT;

    const int tid  = threadIdx.x;
    const int oc_t = tid & 3;            // 4 oc-groups of 8
    const int px_t = tid >> 2;           // 64 px-threads, each owns 2 px
    const int p0y  = px_t >> 4;          // 0..3 (second px at +4 rows)
    const int p0x  = px_t & 15;
    const int x0 = bx * TX, y0 = by * TY;

    unsigned long long acc[2][4];        // [px][oc-pair]
#pragma unroll
    for (int i = 0; i < 2; i++)
#pragma unroll
        for (int j = 0; j < 4; j++) acc[i][j] = 0ull;

    const float* in0 = ref + (size_t)b * C * HW;
    const float* in1 = nbr + (size_t)b * C * HW;

    for (int ch = 0; ch < CIN; ch += ICC) {
        // ---- load input patch [8][10][18] (zero-padded borders) ----
        for (int idx = tid; idx < ICC * (TY+2) * (TX+2); idx += 256) {
            int icl = idx / ((TY+2)*(TX+2));
            int r   = idx % ((TY+2)*(TX+2));
            int py  = r / (TX+2);
            int px  = r % (TX+2);
            int gy = y0 - 1 + py;
            int gx = x0 - 1 + px;
            int ic = ch + icl;
            float v = 0.f;
            if (gy >= 0 && gy < H && gx >= 0 && gx < W) {
                const float* src = (ic < C) ? (in0 + (size_t)ic * HW)
                                            : (in1 + (size_t)(ic - C) * HW);
                v = src[gy * W + gx];
            }
            sIn[icl][py][px] = v;
        }
        // ---- load weights: sW[ks][oc] = w[ocg][ch+icl][kk], ks=icl*9+kk ----
        for (int idx = tid; idx < OCT * 72; idx += 256) {
            int oc = idx / 72;
            int ks = idx % 72;           // consecutive ks -> contiguous global
            int ocg = ocb * OCT + oc;
            float v = 0.f;
            if (ocg < NOFF)      v = off_w [(size_t)ocg * CIN * 9 + (size_t)ch * 9 + ks];
            else if (ocg < NOC)  v = mask_w[(size_t)(ocg - NOFF) * CIN * 9 + (size_t)ch * 9 + ks];
            sW[ks][oc] = v;
        }
        __syncthreads();

        for (int icl = 0; icl < ICC; icl++) {
#pragma unroll
            for (int kk = 0; kk < 9; kk++) {
                const int ki = kk / 3, kj = kk % 3;
                float a0 = sIn[icl][p0y + ki][p0x + kj];
                float a1 = sIn[icl][p0y + 4 + ki][p0x + kj];
                unsigned long long A0, A1;
                PACK2(A0, a0, a0);
                PACK2(A1, a1, a1);
                const ulonglong2* wp =
                    reinterpret_cast<const ulonglong2*>(&sW[icl*9 + kk][oc_t*8]);
                ulonglong2 wA = wp[0];   // oc pairs {0,1},{2,3}
                ulonglong2 wB = wp[1];   // oc pairs {4,5},{6,7}
                FMA_F32X2(acc[0][0], A0, wA.x);
                FMA_F32X2(acc[0][1], A0, wA.y);
                FMA_F32X2(acc[0][2], A0, wB.x);
                FMA_F32X2(acc[0][3], A0, wB.y);
                FMA_F32X2(acc[1][0], A1, wA.x);
                FMA_F32X2(acc[1][1], A1, wA.y);
                FMA_F32X2(acc[1][2], A1, wB.x);
                FMA_F32X2(acc[1][3], A1, wB.y);
            }
        }
        __syncthreads();
    }

    // ---- store (+bias) ----
#pragma unroll
    for (int i = 0; i < 2; i++) {
        int gy = y0 + p0y + i * 4;
        int gx = x0 + p0x;
#pragma unroll
        for (int jp = 0; jp < 4; jp++) {
            float2 f = *reinterpret_cast<float2*>(&acc[i][jp]);
#pragma unroll
            for (int h = 0; h < 2; h++) {
                int ocg = ocb * OCT + oc_t * 8 + jp * 2 + h;
                if (ocg < NOC) {
                    float bv = (ocg < NOFF) ? off_b[ocg] : mask_b[ocg - NOFF];
                    float v = (h == 0) ? f.x : f.y;
                    g_scr[((size_t)(b * NOC + ocg) * H + gy) * W + gx] = v + bv;
                }
            }
        }
    }
}

// ---------------------------------------------------------------------------
// Kernel B: deformable bilinear sampling * sigmoid(mask) -> smem,
// then GEMM vs weight (K=576) + bias.
// Block: 16 pixels of one row; 128 threads.
// Phase-1 task order: p minor -> coalesced scr reads + spatially-coherent
// gather addresses within a warp.
// ---------------------------------------------------------------------------
#define TPX 16
#define KTOT 576
#define ASTR 577   // padded stride (odd -> conflict-free px access)
#define KC 32

__global__ __launch_bounds__(128) void kernB(const float* __restrict__ nbr,
                                             const float* __restrict__ weight,
                                             const float* __restrict__ bias,
                                             float* __restrict__ out)
{
    __shared__ __align__(16) float sA[TPX * ASTR];     // 36928 B
    __shared__ __align__(16) float sWt[KC][68];        // rows 272B (16B mult)

    const int bx = blockIdx.x;           // W/16
    const int y  = blockIdx.y;           // H
    const int b  = blockIdx.z;           // B
    const int x0 = bx * TPX;
    const int tid = threadIdx.x;

    const float* scr = g_scr + (size_t)b * NOC * HW;
    const float* img = nbr   + (size_t)b * C * HW;

    // ---- phase 1: sampled * mask into sA[p][(g*8+c)*9 + k] ----
    for (int task = tid; task < TPX * 72; task += 128) {
        int p  = task & (TPX - 1);       // pixel minor -> coalesced
        int gk = task >> 4;              // 0..71
        int g  = gk / 9;
        int k  = gk - g * 9;
        int x  = x0 + p;
        int base = y * W + x;

        float dy = scr[(size_t)(2*gk)     * HW + base];
        float dx = scr[(size_t)(2*gk + 1) * HW + base];
        float mr = scr[(size_t)(NOFF + gk) * HW + base];
        float m  = 1.f / (1.f + __expf(-mr));

        float ys = dy + (float)(y - 1 + k / 3);
        float xs = dx + (float)(x - 1 + k % 3);
        float yf = floorf(ys), xf = floorf(xs);
        float wy = ys - yf,    wx = xs - xf;
        int yi = (int)yf, xi = (int)xf;

        bool vy0 = (yi >= 0) && (yi < H);
        bool vy1 = (yi + 1 >= 0) && (yi + 1 < H);
        bool vx0 = (xi >= 0) && (xi < W);
        bool vx1 = (xi + 1 >= 0) && (xi + 1 < W);

        float w00 = ((vy0 && vx0) ? (1.f - wy) * (1.f - wx) : 0.f) * m;
        float w01 = ((vy0 && vx1) ? (1.f - wy) * wx         : 0.f) * m;
        float w10 = ((vy1 && vx0) ? wy * (1.f - wx)         : 0.f) * m;
        float w11 = ((vy1 && vx1) ? wy * wx                 : 0.f) * m;

        int yc0 = min(max(yi,     0), H - 1);
        int yc1 = min(max(yi + 1, 0), H - 1);
        int xc0 = min(max(xi,     0), W - 1);
        int xc1 = min(max(xi + 1, 0), W - 1);

        int o00 = yc0 * W + xc0, o01 = yc0 * W + xc1;
        int o10 = yc1 * W + xc0, o11 = yc1 * W + xc1;

        const float* cbase = img + (size_t)(g * CG) * HW;
        float* dst = &sA[p * ASTR + (g * CG) * 9 + k];
#pragma unroll
        for (int c = 0; c < CG; c++) {
            const float* pc = cbase + (size_t)c * HW;
            float v = w00 * __ldg(pc + o00) + w01 * __ldg(pc + o01)
                    + w10 * __ldg(pc + o10) + w11 * __ldg(pc + o11);
            dst[c * 9] = v;
        }
    }
    __syncthreads();

    // ---- phase 2: out[p][o] = sum_k sA[p][k] * weight[o][k] ----
    const int oc_t = tid & 15;   // 16 groups x 4 oc
    const int px_t = tid >> 4;   // 8 -> handles px_t and px_t+8
    unsigned long long acc[2][2];  // [px][oc-pair]
#pragma unroll
    for (int i = 0; i < 2; i++)
#pragma unroll
        for (int j = 0; j < 2; j++) acc[i][j] = 0ull;

    for (int k0 = 0; k0 < KTOT; k0 += KC) {
        for (int idx = tid; idx < KC * 64; idx += 128) {
            int o  = idx / KC;
            int kl = idx % KC;           // consecutive kl -> contiguous global
            sWt[kl][o] = weight[(size_t)o * KTOT + k0 + kl];
        }
        __syncthreads();
#pragma unroll 8
        for (int kl = 0; kl < KC; kl++) {
            float a0 = sA[px_t * ASTR + k0 + kl];
            float a1 = sA[(px_t + 8) * ASTR + k0 + kl];
            unsigned long long A0, A1;
            PACK2(A0, a0, a0);
            PACK2(A1, a1, a1);
            ulonglong2 wv = *reinterpret_cast<const ulonglong2*>(&sWt[kl][oc_t * 4]);
            FMA_F32X2(acc[0][0], A0, wv.x);
            FMA_F32X2(acc[0][1], A0, wv.y);
            FMA_F32X2(acc[1][0], A1, wv.x);
            FMA_F32X2(acc[1][1], A1, wv.y);
        }
        __syncthreads();
    }

    // ---- store + bias ----
#pragma unroll
    for (int i = 0; i < 2; i++) {
        int p = px_t + i * 8;
        int x = x0 + p;
#pragma unroll
        for (int jp = 0; jp < 2; jp++) {
            float2 f = *reinterpret_cast<float2*>(&acc[i][jp]);
#pragma unroll
            for (int h = 0; h < 2; h++) {
                int o = oc_t * 4 + jp * 2 + h;
                float v = (h == 0) ? f.x : f.y;
                out[((size_t)(b * C + o) * H + y) * W + x] = v + bias[o];
            }
        }
    }
}

// ---------------------------------------------------------------------------
extern "C" void kernel_launch(void* const* d_in, const int* in_sizes, int n_in,
                              void* d_out, int out_size) {
    const float* ref    = (const float*)d_in[0];
    const float* nbr    = (const float*)d_in[1];
    const float* off_w  = (const float*)d_in[2];
    const float* off_b  = (const float*)d_in[3];
    const float* mask_w = (const float*)d_in[4];
    const float* mask_b = (const float*)d_in[5];
    const float* weight = (const float*)d_in[6];
    const float* bias   = (const float*)d_in[7];
    float* out = (float*)d_out;

    dim3 gA(W / TX, H / TY, BB * OCB_COUNT);
    convA<<<gA, 256>>>(ref, nbr, off_w, off_b, mask_w, mask_b);

    dim3 gB(W / TPX, H, BB);
    kernB<<<gB, 128>>>(nbr, weight, bias, out);
}

// round 6
// speedup vs baseline: 1.3282x; 1.1475x over previous
#include <cuda_runtime.h>
#include <math.h>
#include <stdint.h>

#define BB  2
#define C   64
#define H   256
#define W   256
#define HW  (H*W)
#define KK  9
#define DG  8
#define CG  8
#define CIN 128
#define NOFF 144
#define NMSK 72
#define NOC  216   // 144 offset + 72 mask channels

// Packed fp32x2 FMA (Blackwell): 2 fp32 MACs per FMA-pipe slot.
#define FMA_F32X2(acc, a, b) \
    asm("fma.rn.f32x2 %0, %1, %2, %0;" : "+l"(acc) : "l"(a), "l"(b))
#define PACK2(out, lo, hi) \
    asm("mov.b64 %0, {%1, %2};" : "=l"(out) : "f"(lo), "f"(hi))

// Scratch for raw conv outputs: [b][ch(216)][y][x]
__device__ float g_scr[BB * NOC * H * W];

// ---------------------------------------------------------------------------
// Kernel A: fused offset+mask 3x3 conv over concat(ref, neighbour) (128 ch in)
// Block tile: 32x8 pixels, 32 out channels. 256 threads.
// Thread tile: 4 px (consecutive x) x 8 oc. Activations register-cached.
// ---------------------------------------------------------------------------
#define ATX 32
#define ATY 8
#define OCT 32
#define ICC 8
#define OCB_COUNT 7   // ceil(216/32)

__global__ __launch_bounds__(256) void convA(const float* __restrict__ ref,
                                             const float* __restrict__ nbr,
                                             const float* __restrict__ off_w,
                                             const float* __restrict__ off_b,
                                             const float* __restrict__ mask_w,
                                             const float* __restrict__ mask_b)
{
    __shared__ __align__(16) float sIn[ICC][ATY+2][ATX+4];  // [8][10][36]
    __shared__ __align__(16) float sW[ICC*9][36];           // rows 144B

    const int bx  = blockIdx.x;          // W/32
    const int by  = blockIdx.y;          // H/8
    const int bz  = blockIdx.z;          // b*7 + ocb
    const int b   = bz / OCB_COUNT;
    const int ocb = bz % OCB_COUNT;

    const int tid  = threadIdx.x;
    const int oc_t = tid & 3;            // 4 oc-groups of 8
    const int px_t = tid >> 2;           // 64 px-threads: 4 px each
    const int r    = px_t >> 3;          // row 0..7
    const int cq   = (px_t & 7) * 4;     // col base 0..28
    const int x0 = bx * ATX, y0 = by * ATY;

    unsigned long long acc[4][4];        // [px][oc-pair]
#pragma unroll
    for (int i = 0; i < 4; i++)
#pragma unroll
        for (int j = 0; j < 4; j++) acc[i][j] = 0ull;

    const float* in0 = ref + (size_t)b * C * HW;
    const float* in1 = nbr + (size_t)b * C * HW;

    for (int ch = 0; ch < CIN; ch += ICC) {
        // ---- load input patch [8][10][34] (zero-padded borders) ----
        for (int idx = tid; idx < ICC * (ATY+2) * (ATX+2); idx += 256) {
            int icl = idx / ((ATY+2)*(ATX+2));
            int rem = idx % ((ATY+2)*(ATX+2));
            int py  = rem / (ATX+2);
            int px  = rem % (ATX+2);
            int gy = y0 - 1 + py;
            int gx = x0 - 1 + px;
            int ic = ch + icl;
            float v = 0.f;
            if (gy >= 0 && gy < H && gx >= 0 && gx < W) {
                const float* src = (ic < C) ? (in0 + (size_t)ic * HW)
                                            : (in1 + (size_t)(ic - C) * HW);
                v = src[gy * W + gx];
            }
            sIn[icl][py][px] = v;
        }
        // ---- load weights: sW[ks][oc] = w[ocg][ch+icl][kk], ks=icl*9+kk ----
        for (int idx = tid; idx < OCT * 72; idx += 256) {
            int oc = idx / 72;
            int ks = idx % 72;           // consecutive ks -> contiguous global
            int ocg = ocb * OCT + oc;
            float v = 0.f;
            if (ocg < NOFF)      v = off_w [(size_t)ocg * CIN * 9 + (size_t)ch * 9 + ks];
            else if (ocg < NOC)  v = mask_w[(size_t)(ocg - NOFF) * CIN * 9 + (size_t)ch * 9 + ks];
            sW[ks][oc] = v;
        }
        __syncthreads();

#pragma unroll
        for (int icl = 0; icl < ICC; icl++) {
            // register-cache the 3x6 activation window
            float rowv[3][6];
#pragma unroll
            for (int rr = 0; rr < 3; rr++) {
                float4 v4 = *reinterpret_cast<const float4*>(&sIn[icl][r + rr][cq]);
                float2 v2 = *reinterpret_cast<const float2*>(&sIn[icl][r + rr][cq + 4]);
                rowv[rr][0] = v4.x; rowv[rr][1] = v4.y;
                rowv[rr][2] = v4.z; rowv[rr][3] = v4.w;
                rowv[rr][4] = v2.x; rowv[rr][5] = v2.y;
            }
#pragma unroll
            for (int kk = 0; kk < 9; kk++) {
                const int ki = kk / 3, kj = kk % 3;
                unsigned long long A[4];
#pragma unroll
                for (int px = 0; px < 4; px++) {
                    float a = rowv[ki][kj + px];
                    PACK2(A[px], a, a);
                }
                const ulonglong2* wp =
                    reinterpret_cast<const ulonglong2*>(&sW[icl*9 + kk][oc_t*8]);
                ulonglong2 wA = wp[0];   // oc pairs {0,1},{2,3}
                ulonglong2 wB = wp[1];   // oc pairs {4,5},{6,7}
#pragma unroll
                for (int px = 0; px < 4; px++) {
                    FMA_F32X2(acc[px][0], A[px], wA.x);
                    FMA_F32X2(acc[px][1], A[px], wA.y);
                    FMA_F32X2(acc[px][2], A[px], wB.x);
                    FMA_F32X2(acc[px][3], A[px], wB.y);
                }
            }
        }
        __syncthreads();
    }

    // ---- store (+bias): per oc, 4 consecutive px -> STG.128 ----
    {
        int gy = y0 + r;
        int gx = x0 + cq;
#pragma unroll
        for (int jp = 0; jp < 4; jp++) {
#pragma unroll
            for (int h = 0; h < 2; h++) {
                int ocg = ocb * OCT + oc_t * 8 + jp * 2 + h;
                if (ocg < NOC) {
                    float bv = (ocg < NOFF) ? off_b[ocg] : mask_b[ocg - NOFF];
                    float4 v;
                    float2 f0 = *reinterpret_cast<float2*>(&acc[0][jp]);
                    float2 f1 = *reinterpret_cast<float2*>(&acc[1][jp]);
                    float2 f2 = *reinterpret_cast<float2*>(&acc[2][jp]);
                    float2 f3 = *reinterpret_cast<float2*>(&acc[3][jp]);
                    v.x = ((h == 0) ? f0.x : f0.y) + bv;
                    v.y = ((h == 0) ? f1.x : f1.y) + bv;
                    v.z = ((h == 0) ? f2.x : f2.y) + bv;
                    v.w = ((h == 0) ? f3.x : f3.y) + bv;
                    *reinterpret_cast<float4*>(
                        &g_scr[((size_t)(b * NOC + ocg) * H + gy) * W + gx]) = v;
                }
            }
        }
    }
}

// ---------------------------------------------------------------------------
// Kernel B: deformable bilinear sampling * sigmoid(mask), fused per-group GEMM.
// Block: 64 pixels of one row; 256 threads; loop over 8 deform groups:
//   phase 1: sample group g (72 K-values/px) into sAg
//   phase 2: acc[oc] += sAg . weight[:, g*72 : g*72+72]   (regs, f32x2)
// ---------------------------------------------------------------------------
#define BPX 64
#define KTOT 576
#define GSTR 73    // sAg row stride
#define WSTR 68    // sWg row stride (272B, 16B multiple)

__global__ __launch_bounds__(256) void kernB(const float* __restrict__ nbr,
                                             const float* __restrict__ weight,
                                             const float* __restrict__ bias,
                                             float* __restrict__ out)
{
    __shared__ __align__(16) float sAg[BPX * GSTR];   // 64*73*4 = 18688 B
    __shared__ __align__(16) float sWg[72 * WSTR];    // 72*68*4 = 19584 B

    const int bx = blockIdx.x;           // W/64
    const int y  = blockIdx.y;           // H
    const int b  = blockIdx.z;           // B
    const int x0 = bx * BPX;
    const int tid = threadIdx.x;

    const float* scr = g_scr + (size_t)b * NOC * HW;
    const float* img = nbr   + (size_t)b * C * HW;

    const int oc_t = tid & 3;            // 4 oc-groups of 16
    const int px_t = tid >> 2;           // 64 px-threads, 1 px each

    unsigned long long acc[8];           // 16 oc as 8 pairs
#pragma unroll
    for (int j = 0; j < 8; j++) acc[j] = 0ull;

    for (int g = 0; g < DG; g++) {
        // ---- phase 1: sample group g into sAg[p][c*9+k] ----
        for (int t = tid; t < BPX * 9; t += 256) {
            int p = t & (BPX - 1);       // pixel minor -> coalesced
            int k = t >> 6;              // 0..8
            int gk = g * 9 + k;
            int x  = x0 + p;
            int base = y * W + x;

            float dy = scr[(size_t)(2*gk)      * HW + base];
            float dx = scr[(size_t)(2*gk + 1)  * HW + base];
            float mr = scr[(size_t)(NOFF + gk) * HW + base];
            float m  = 1.f / (1.f + __expf(-mr));

            float ys = dy + (float)(y - 1 + k / 3);
            float xs = dx + (float)(x - 1 + k % 3);
            float yf = floorf(ys), xf = floorf(xs);
            float wy = ys - yf,    wx = xs - xf;
            int yi = (int)yf, xi = (int)xf;

            bool vy0 = (yi >= 0) && (yi < H);
            bool vy1 = (yi + 1 >= 0) && (yi + 1 < H);
            bool vx0 = (xi >= 0) && (xi < W);
            bool vx1 = (xi + 1 >= 0) && (xi + 1 < W);

            float w00 = ((vy0 && vx0) ? (1.f - wy) * (1.f - wx) : 0.f) * m;
            float w01 = ((vy0 && vx1) ? (1.f - wy) * wx         : 0.f) * m;
            float w10 = ((vy1 && vx0) ? wy * (1.f - wx)         : 0.f) * m;
            float w11 = ((vy1 && vx1) ? wy * wx                 : 0.f) * m;

            int yc0 = min(max(yi,     0), H - 1);
            int yc1 = min(max(yi + 1, 0), H - 1);
            int xc0 = min(max(xi,     0), W - 1);
            int xc1 = min(max(xi + 1, 0), W - 1);

            int o00 = yc0 * W + xc0, o01 = yc0 * W + xc1;
            int o10 = yc1 * W + xc0, o11 = yc1 * W + xc1;

            const float* cbase = img + (size_t)(g * CG) * HW;
            float* dst = &sAg[p * GSTR + k];
#pragma unroll
            for (int c = 0; c < CG; c++) {
                const float* pc = cbase + (size_t)c * HW;
                float v = w00 * __ldg(pc + o00) + w01 * __ldg(pc + o01)
                        + w10 * __ldg(pc + o10) + w11 * __ldg(pc + o11);
                dst[c * 9] = v;
            }
        }
        // ---- stage weight slice: sWg[kl][o] = weight[o][g*72+kl] ----
        for (int idx = tid; idx < 72 * 64; idx += 256) {
            int o  = idx / 72;
            int kl = idx % 72;           // contiguous global reads
            sWg[kl * WSTR + o] = weight[(size_t)o * KTOT + g * 72 + kl];
        }
        __syncthreads();

        // ---- phase 2: acc[16 oc] += sAg[px_t][.] . sWg[.][oc] ----
#pragma unroll
        for (int kl = 0; kl < 72; kl++) {
            float a = sAg[px_t * GSTR + kl];
            unsigned long long A;
            PACK2(A, a, a);
            const ulonglong2* wp =
                reinterpret_cast<const ulonglong2*>(&sWg[kl * WSTR + oc_t * 16]);
            ulonglong2 w0 = wp[0];
            ulonglong2 w1 = wp[1];
            FMA_F32X2(acc[0], A, w0.x);
            FMA_F32X2(acc[1], A, w0.y);
            FMA_F32X2(acc[2], A, w1.x);
            FMA_F32X2(acc[3], A, w1.y);
            const ulonglong2* wq =
                reinterpret_cast<const ulonglong2*>(&sWg[kl * WSTR + oc_t * 16 + 8]);
            ulonglong2 w2 = wq[0];
            ulonglong2 w3 = wq[1];
            FMA_F32X2(acc[4], A, w2.x);
            FMA_F32X2(acc[5], A, w2.y);
            FMA_F32X2(acc[6], A, w3.x);
            FMA_F32X2(acc[7], A, w3.y);
        }
        __syncthreads();
    }

    // ---- transpose via smem (reuse sWg) and store coalesced + bias ----
    float* sOut = sWg;                   // [64 oc][65]
#pragma unroll
    for (int jp = 0; jp < 8; jp++) {
        float2 f = *reinterpret_cast<float2*>(&acc[jp]);
        int o0 = oc_t * 16 + jp * 2;
        sOut[(o0    ) * 65 + px_t] = f.x;
        sOut[(o0 + 1) * 65 + px_t] = f.y;
    }
    __syncthreads();
    for (int idx = tid; idx < 64 * BPX; idx += 256) {
        int o = idx >> 6;
        int p = idx & (BPX - 1);
        out[((size_t)(b * C + o) * H + y) * W + x0 + p] = sOut[o * 65 + p] + bias[o];
    }
}

// ---------------------------------------------------------------------------
extern "C" void kernel_launch(void* const* d_in, const int* in_sizes, int n_in,
                              void* d_out, int out_size) {
    const float* ref    = (const float*)d_in[0];
    const float* nbr    = (const float*)d_in[1];
    const float* off_w  = (const float*)d_in[2];
    const float* off_b  = (const float*)d_in[3];
    const float* mask_w = (const float*)d_in[4];
    const float* mask_b = (const float*)d_in[5];
    const float* weight = (const float*)d_in[6];
    const float* bias   = (const float*)d_in[7];
    float* out = (float*)d_out;

    dim3 gA(W / ATX, H / ATY, BB * OCB_COUNT);
    convA<<<gA, 256>>>(ref, nbr, off_w, off_b, mask_w, mask_b);

    dim3 gB(W / BPX, H, BB);
    kernB<<<gB, 256>>>(nbr, weight, bias, out);
}

// round 7
// speedup vs baseline: 1.3353x; 1.0053x over previous
#include <cuda_runtime.h>
#include <math.h>
#include <stdint.h>

#define BB  2
#define C   64
#define H   256
#define W   256
#define HW  (H*W)
#define KK  9
#define DG  8
#define CG  8
#define CIN 128
#define NOFF 144
#define NMSK 72
#define NOC  216   // 144 offset + 72 mask channels

// Packed fp32x2 FMA (Blackwell): 2 fp32 MACs per FMA-pipe slot.
#define FMA_F32X2(acc, a, b) \
    asm("fma.rn.f32x2 %0, %1, %2, %0;" : "+l"(acc) : "l"(a), "l"(b))
#define PACK2(out, lo, hi) \
    asm("mov.b64 %0, {%1, %2};" : "=l"(out) : "f"(lo), "f"(hi))

// Scratch for raw conv outputs: [b][ch(216)][y][x]
__device__ float g_scr[BB * NOC * H * W];

// ---------------------------------------------------------------------------
// Kernel A: fused offset+mask 3x3 conv over concat(ref, neighbour) (128 ch in)
// Block tile: 32x8 pixels, 32 out channels. 256 threads.
// Thread tile: 4 px x 8 oc. Activations stored DUPLICATED (float2{v,v}) in
// smem so LDS.128 yields packed f32x2 operands directly (no MOV packs).
// Global loads software-pipelined through registers (prefetch next chunk
// during current chunk's compute).
// ---------------------------------------------------------------------------
#define ATX 32
#define ATY 8
#define OCT 32
#define ICC 8
#define OCB_COUNT 7     // ceil(216/32)
#define IN_ELEMS (ICC * (ATY+2) * (ATX+2))   // 2720
#define IN_IT    11                          // ceil(2720/256)
#define W_ELEMS  (OCT * ICC * 9)             // 2304
#define W_IT     9                           // 2304/256

__global__ __launch_bounds__(256, 2) void convA(const float* __restrict__ ref,
                                                const float* __restrict__ nbr,
                                                const float* __restrict__ off_w,
                                                const float* __restrict__ off_b,
                                                const float* __restrict__ mask_w,
                                                const float* __restrict__ mask_b)
{
    __shared__ __align__(16) float2 sIn2[ICC][ATY+2][36];  // dup layout, 23040B
    __shared__ __align__(16) float  sW[ICC*9][36];         // 10368B

    const int bx  = blockIdx.x;          // W/32
    const int by  = blockIdx.y;          // H/8
    const int bz  = blockIdx.z;          // b*7 + ocb
    const int b   = bz / OCB_COUNT;
    const int ocb = bz % OCB_COUNT;

    const int tid  = threadIdx.x;
    const int oc_t = tid & 3;            // 4 oc-groups of 8
    const int px_t = tid >> 2;           // 64 px-threads: 4 px each
    const int r    = px_t >> 3;          // row 0..7
    const int cq   = (px_t & 7) * 4;     // col base 0..28
    const int x0 = bx * ATX, y0 = by * ATY;

    unsigned long long acc[4][4];        // [px][oc-pair]
#pragma unroll
    for (int i = 0; i < 4; i++)
#pragma unroll
        for (int j = 0; j < 4; j++) acc[i][j] = 0ull;

    const float* in0 = ref + (size_t)b * C * HW;
    const float* in1 = nbr + (size_t)b * C * HW;

    float inv[IN_IT];
    float wv[W_IT];

    // ---- prefetch chunk 0 ----
#pragma unroll
    for (int it = 0; it < IN_IT; it++) {
        int idx = tid + it * 256;
        float v = 0.f;
        if (idx < IN_ELEMS) {
            int icl = idx / ((ATY+2)*(ATX+2));
            int rem = idx % ((ATY+2)*(ATX+2));
            int py  = rem / (ATX+2);
            int px  = rem % (ATX+2);
            int gy = y0 - 1 + py;
            int gx = x0 - 1 + px;
            if (gy >= 0 && gy < H && gx >= 0 && gx < W) {
                const float* src = (icl < C) ? (in0 + (size_t)icl * HW)
                                             : (in1 + (size_t)(icl - C) * HW);
                v = src[gy * W + gx];
            }
        }
        inv[it] = v;
    }
#pragma unroll
    for (int it = 0; it < W_IT; it++) {
        int idx = tid + it * 256;
        int oc = idx / 72;
        int ks = idx % 72;
        int ocg = ocb * OCT + oc;
        float v = 0.f;
        if (ocg < NOFF)      v = off_w [(size_t)ocg * CIN * 9 + ks];
        else if (ocg < NOC)  v = mask_w[(size_t)(ocg - NOFF) * CIN * 9 + ks];
        wv[it] = v;
    }

    for (int ch = 0; ch < CIN; ch += ICC) {
        __syncthreads();   // previous compute done with smem
        // ---- store prefetched chunk to smem ----
#pragma unroll
        for (int it = 0; it < IN_IT; it++) {
            int idx = tid + it * 256;
            if (idx < IN_ELEMS) {
                int icl = idx / ((ATY+2)*(ATX+2));
                int rem = idx % ((ATY+2)*(ATX+2));
                int py  = rem / (ATX+2);
                int px  = rem % (ATX+2);
                sIn2[icl][py][px] = make_float2(inv[it], inv[it]);
            }
        }
#pragma unroll
        for (int it = 0; it < W_IT; it++) {
            int idx = tid + it * 256;
            sW[idx % 72][idx / 72] = wv[it];
        }
        __syncthreads();

        // ---- prefetch next chunk (LDGs overlap with compute below) ----
        int chn = ch + ICC;
        if (chn < CIN) {
#pragma unroll
            for (int it = 0; it < IN_IT; it++) {
                int idx = tid + it * 256;
                float v = 0.f;
                if (idx < IN_ELEMS) {
                    int icl = idx / ((ATY+2)*(ATX+2));
                    int rem = idx % ((ATY+2)*(ATX+2));
                    int py  = rem / (ATX+2);
                    int px  = rem % (ATX+2);
                    int gy = y0 - 1 + py;
                    int gx = x0 - 1 + px;
                    int ic = chn + icl;
                    if (gy >= 0 && gy < H && gx >= 0 && gx < W) {
                        const float* src = (ic < C) ? (in0 + (size_t)ic * HW)
                                                    : (in1 + (size_t)(ic - C) * HW);
                        v = src[gy * W + gx];
                    }
                }
                inv[it] = v;
            }
#pragma unroll
            for (int it = 0; it < W_IT; it++) {
                int idx = tid + it * 256;
                int oc = idx / 72;
                int ks = idx % 72;
                int ocg = ocb * OCT + oc;
                float v = 0.f;
                if (ocg < NOFF)      v = off_w [(size_t)ocg * CIN * 9 + (size_t)chn * 9 + ks];
                else if (ocg < NOC)  v = mask_w[(size_t)(ocg - NOFF) * CIN * 9 + (size_t)chn * 9 + ks];
                wv[it] = v;
            }
        }

        // ---- compute chunk: pure LDS.128 + FMA2 ----
#pragma unroll
        for (int icl = 0; icl < ICC; icl++) {
            unsigned long long rv[3][6];     // duplicated activations {a,a}
#pragma unroll
            for (int rr = 0; rr < 3; rr++) {
                const ulonglong2* rp =
                    reinterpret_cast<const ulonglong2*>(&sIn2[icl][r + rr][cq]);
                ulonglong2 u0 = rp[0], u1 = rp[1], u2 = rp[2];
                rv[rr][0] = u0.x; rv[rr][1] = u0.y;
                rv[rr][2] = u1.x; rv[rr][3] = u1.y;
                rv[rr][4] = u2.x; rv[rr][5] = u2.y;
            }
#pragma unroll
            for (int kk = 0; kk < 9; kk++) {
                const int ki = kk / 3, kj = kk % 3;
                const ulonglong2* wp =
                    reinterpret_cast<const ulonglong2*>(&sW[icl*9 + kk][oc_t*8]);
                ulonglong2 wA = wp[0];   // oc pairs {0,1},{2,3}
                ulonglong2 wB = wp[1];   // oc pairs {4,5},{6,7}
#pragma unroll
                for (int px = 0; px < 4; px++) {
                    unsigned long long A = rv[ki][kj + px];
                    FMA_F32X2(acc[px][0], A, wA.x);
                    FMA_F32X2(acc[px][1], A, wA.y);
                    FMA_F32X2(acc[px][2], A, wB.x);
                    FMA_F32X2(acc[px][3], A, wB.y);
                }
            }
        }
    }

    // ---- store (+bias): per oc, 4 consecutive px -> STG.128 ----
    {
        int gy = y0 + r;
        int gx = x0 + cq;
#pragma unroll
        for (int jp = 0; jp < 4; jp++) {
#pragma unroll
            for (int h = 0; h < 2; h++) {
                int ocg = ocb * OCT + oc_t * 8 + jp * 2 + h;
                if (ocg < NOC) {
                    float bv = (ocg < NOFF) ? off_b[ocg] : mask_b[ocg - NOFF];
                    float4 v;
                    float2 f0 = *reinterpret_cast<float2*>(&acc[0][jp]);
                    float2 f1 = *reinterpret_cast<float2*>(&acc[1][jp]);
                    float2 f2 = *reinterpret_cast<float2*>(&acc[2][jp]);
                    float2 f3 = *reinterpret_cast<float2*>(&acc[3][jp]);
                    v.x = ((h == 0) ? f0.x : f0.y) + bv;
                    v.y = ((h == 0) ? f1.x : f1.y) + bv;
                    v.z = ((h == 0) ? f2.x : f2.y) + bv;
                    v.w = ((h == 0) ? f3.x : f3.y) + bv;
                    *reinterpret_cast<float4*>(
                        &g_scr[((size_t)(b * NOC + ocg) * H + gy) * W + gx]) = v;
                }
            }
        }
    }
}

// ---------------------------------------------------------------------------
// Kernel B: unchanged from R5 (near its gather-wavefront floor).
// ---------------------------------------------------------------------------
#define BPX 64
#define KTOT 576
#define GSTR 73    // sAg row stride
#define WSTR 68    // sWg row stride (272B, 16B multiple)

__global__ __launch_bounds__(256) void kernB(const float* __restrict__ nbr,
                                             const float* __restrict__ weight,
                                             const float* __restrict__ bias,
                                             float* __restrict__ out)
{
    __shared__ __align__(16) float sAg[BPX * GSTR];   // 18688 B
    __shared__ __align__(16) float sWg[72 * WSTR];    // 19584 B

    const int bx = blockIdx.x;           // W/64
    const int y  = blockIdx.y;           // H
    const int b  = blockIdx.z;           // B
    const int x0 = bx * BPX;
    const int tid = threadIdx.x;

    const float* scr = g_scr + (size_t)b * NOC * HW;
    const float* img = nbr   + (size_t)b * C * HW;

    const int oc_t = tid & 3;            // 4 oc-groups of 16
    const int px_t = tid >> 2;           // 64 px-threads, 1 px each

    unsigned long long acc[8];           // 16 oc as 8 pairs
#pragma unroll
    for (int j = 0; j < 8; j++) acc[j] = 0ull;

    for (int g = 0; g < DG; g++) {
        // ---- phase 1: sample group g into sAg[p][c*9+k] ----
        for (int t = tid; t < BPX * 9; t += 256) {
            int p = t & (BPX - 1);       // pixel minor -> coalesced
            int k = t >> 6;              // 0..8
            int gk = g * 9 + k;
            int x  = x0 + p;
            int base = y * W + x;

            float dy = scr[(size_t)(2*gk)      * HW + base];
            float dx = scr[(size_t)(2*gk + 1)  * HW + base];
            float mr = scr[(size_t)(NOFF + gk) * HW + base];
            float m  = 1.f / (1.f + __expf(-mr));

            float ys = dy + (float)(y - 1 + k / 3);
            float xs = dx + (float)(x - 1 + k % 3);
            float yf = floorf(ys), xf = floorf(xs);
            float wy = ys - yf,    wx = xs - xf;
            int yi = (int)yf, xi = (int)xf;

            bool vy0 = (yi >= 0) && (yi < H);
            bool vy1 = (yi + 1 >= 0) && (yi + 1 < H);
            bool vx0 = (xi >= 0) && (xi < W);
            bool vx1 = (xi + 1 >= 0) && (xi + 1 < W);

            float w00 = ((vy0 && vx0) ? (1.f - wy) * (1.f - wx) : 0.f) * m;
            float w01 = ((vy0 && vx1) ? (1.f - wy) * wx         : 0.f) * m;
            float w10 = ((vy1 && vx0) ? wy * (1.f - wx)         : 0.f) * m;
            float w11 = ((vy1 && vx1) ? wy * wx                 : 0.f) * m;

            int yc0 = min(max(yi,     0), H - 1);
            int yc1 = min(max(yi + 1, 0), H - 1);
            int xc0 = min(max(xi,     0), W - 1);
            int xc1 = min(max(xi + 1, 0), W - 1);

            int o00 = yc0 * W + xc0, o01 = yc0 * W + xc1;
            int o10 = yc1 * W + xc0, o11 = yc1 * W + xc1;

            const float* cbase = img + (size_t)(g * CG) * HW;
            float* dst = &sAg[p * GSTR + k];
#pragma unroll
            for (int c = 0; c < CG; c++) {
                const float* pc = cbase + (size_t)c * HW;
                float v = w00 * __ldg(pc + o00) + w01 * __ldg(pc + o01)
                        + w10 * __ldg(pc + o10) + w11 * __ldg(pc + o11);
                dst[c * 9] = v;
            }
        }
        // ---- stage weight slice: sWg[kl][o] = weight[o][g*72+kl] ----
        for (int idx = tid; idx < 72 * 64; idx += 256) {
            int o  = idx / 72;
            int kl = idx % 72;           // contiguous global reads
            sWg[kl * WSTR + o] = weight[(size_t)o * KTOT + g * 72 + kl];
        }
        __syncthreads();

        // ---- phase 2: acc[16 oc] += sAg[px_t][.] . sWg[.][oc] ----
#pragma unroll
        for (int kl = 0; kl < 72; kl++) {
            float a = sAg[px_t * GSTR + kl];
            unsigned long long A;
            PACK2(A, a, a);
            const ulonglong2* wp =
                reinterpret_cast<const ulonglong2*>(&sWg[kl * WSTR + oc_t * 16]);
            ulonglong2 w0 = wp[0];
            ulonglong2 w1 = wp[1];
            FMA_F32X2(acc[0], A, w0.x);
            FMA_F32X2(acc[1], A, w0.y);
            FMA_F32X2(acc[2], A, w1.x);
            FMA_F32X2(acc[3], A, w1.y);
            const ulonglong2* wq =
                reinterpret_cast<const ulonglong2*>(&sWg[kl * WSTR + oc_t * 16 + 8]);
            ulonglong2 w2 = wq[0];
            ulonglong2 w3 = wq[1];
            FMA_F32X2(acc[4], A, w2.x);
            FMA_F32X2(acc[5], A, w2.y);
            FMA_F32X2(acc[6], A, w3.x);
            FMA_F32X2(acc[7], A, w3.y);
        }
        __syncthreads();
    }

    // ---- transpose via smem (reuse sWg) and store coalesced + bias ----
    float* sOut = sWg;                   // [64 oc][65]
#pragma unroll
    for (int jp = 0; jp < 8; jp++) {
        float2 f = *reinterpret_cast<float2*>(&acc[jp]);
        int o0 = oc_t * 16 + jp * 2;
        sOut[(o0    ) * 65 + px_t] = f.x;
        sOut[(o0 + 1) * 65 + px_t] = f.y;
    }
    __syncthreads();
    for (int idx = tid; idx < 64 * BPX; idx += 256) {
        int o = idx >> 6;
        int p = idx & (BPX - 1);
        out[((size_t)(b * C + o) * H + y) * W + x0 + p] = sOut[o * 65 + p] + bias[o];
    }
}

// ---------------------------------------------------------------------------
extern "C" void kernel_launch(void* const* d_in, const int* in_sizes, int n_in,
                              void* d_out, int out_size) {
    const float* ref    = (const float*)d_in[0];
    const float* nbr    = (const float*)d_in[1];
    const float* off_w  = (const float*)d_in[2];
    const float* off_b  = (const float*)d_in[3];
    const float* mask_w = (const float*)d_in[4];
    const float* mask_b = (const float*)d_in[5];
    const float* weight = (const float*)d_in[6];
    const float* bias   = (const float*)d_in[7];
    float* out = (float*)d_out;

    dim3 gA(W / ATX, H / ATY, BB * OCB_COUNT);
    convA<<<gA, 256>>>(ref, nbr, off_w, off_b, mask_w, mask_b);

    dim3 gB(W / BPX, H, BB);
    kernB<<<gB, 256>>>(nbr, weight, bias, out);
}

// round 8
// speedup vs baseline: 1.4795x; 1.1080x over previous
#include <cuda_runtime.h>
#include <math.h>
#include <stdint.h>

#define BB  2
#define C   64
#define H   256
#define W   256
#define HW  (H*W)
#define KK  9
#define DG  8
#define CG  8
#define CIN 128
#define NOFF 144
#define NMSK 72
#define NOC  216   // 144 offset + 72 mask channels

// Packed fp32x2 FMA (Blackwell): 2 fp32 MACs per FMA-pipe slot.
#define FMA_F32X2(acc, a, b) \
    asm("fma.rn.f32x2 %0, %1, %2, %0;" : "+l"(acc) : "l"(a), "l"(b))
#define PACK2(out, lo, hi) \
    asm("mov.b64 %0, {%1, %2};" : "=l"(out) : "f"(lo), "f"(hi))

// Scratch for raw conv outputs: [b][ch(216)][y][x]
__device__ float g_scr[BB * NOC * H * W];
// neighbour transposed per deform-group: [b][g][y][x][8ch]
__device__ float g_tr[BB * DG * H * W * CG];

// ---------------------------------------------------------------------------
// Transpose kernel: nbr [b][c][y][x] -> g_tr [b][g][y][x][c8]
// ---------------------------------------------------------------------------
__global__ __launch_bounds__(256) void transp(const float* __restrict__ nbr)
{
    const int x  = blockIdx.x * 32 + (threadIdx.x & 31);
    const int gi = threadIdx.x >> 5;      // 0..7 group
    const int y  = blockIdx.y;
    const int b  = blockIdx.z;

    const float* src = nbr + ((size_t)(b * C + gi * CG) * HW) + y * W + x;
    float4 a, q;
    a.x = src[0];        a.y = src[(size_t)HW];
    a.z = src[2*(size_t)HW]; a.w = src[3*(size_t)HW];
    q.x = src[4*(size_t)HW]; q.y = src[5*(size_t)HW];
    q.z = src[6*(size_t)HW]; q.w = src[7*(size_t)HW];

    float* dst = g_tr + ((size_t)(b * DG + gi) * HW + y * W + x) * CG;
    *reinterpret_cast<float4*>(dst)     = a;
    *reinterpret_cast<float4*>(dst + 4) = q;
}

// ---------------------------------------------------------------------------
// Kernel A: fused offset+mask 3x3 conv (unchanged from R6; at fp32 floor)
// ---------------------------------------------------------------------------
#define ATX 32
#define ATY 8
#define OCT 32
#define ICC 8
#define OCB_COUNT 7
#define IN_ELEMS (ICC * (ATY+2) * (ATX+2))   // 2720
#define IN_IT    11
#define W_IT     9

__global__ __launch_bounds__(256, 2) void convA(const float* __restrict__ ref,
                                                const float* __restrict__ nbr,
                                                const float* __restrict__ off_w,
                                                const float* __restrict__ off_b,
                                                const float* __restrict__ mask_w,
                                                const float* __restrict__ mask_b)
{
    __shared__ __align__(16) float2 sIn2[ICC][ATY+2][36];
    __shared__ __align__(16) float  sW[ICC*9][36];

    const int bx  = blockIdx.x;
    const int by  = blockIdx.y;
    const int bz  = blockIdx.z;
    const int b   = bz / OCB_COUNT;
    const int ocb = bz % OCB_COUNT;

    const int tid  = threadIdx.x;
    const int oc_t = tid & 3;
    const int px_t = tid >> 2;
    const int r    = px_t >> 3;
    const int cq   = (px_t & 7) * 4;
    const int x0 = bx * ATX, y0 = by * ATY;

    unsigned long long acc[4][4];
#pragma unroll
    for (int i = 0; i < 4; i++)
#pragma unroll
        for (int j = 0; j < 4; j++) acc[i][j] = 0ull;

    const float* in0 = ref + (size_t)b * C * HW;
    const float* in1 = nbr + (size_t)b * C * HW;

    float inv[IN_IT];
    float wv[W_IT];

#pragma unroll
    for (int it = 0; it < IN_IT; it++) {
        int idx = tid + it * 256;
        float v = 0.f;
        if (idx < IN_ELEMS) {
            int icl = idx / ((ATY+2)*(ATX+2));
            int rem = idx % ((ATY+2)*(ATX+2));
            int py  = rem / (ATX+2);
            int px  = rem % (ATX+2);
            int gy = y0 - 1 + py;
            int gx = x0 - 1 + px;
            if (gy >= 0 && gy < H && gx >= 0 && gx < W) {
                const float* src = (icl < C) ? (in0 + (size_t)icl * HW)
                                             : (in1 + (size_t)(icl - C) * HW);
                v = src[gy * W + gx];
            }
        }
        inv[it] = v;
    }
#pragma unroll
    for (int it = 0; it < W_IT; it++) {
        int idx = tid + it * 256;
        int oc = idx / 72;
        int ks = idx % 72;
        int ocg = ocb * OCT + oc;
        float v = 0.f;
        if (ocg < NOFF)      v = off_w [(size_t)ocg * CIN * 9 + ks];
        else if (ocg < NOC)  v = mask_w[(size_t)(ocg - NOFF) * CIN * 9 + ks];
        wv[it] = v;
    }

    for (int ch = 0; ch < CIN; ch += ICC) {
        __syncthreads();
#pragma unroll
        for (int it = 0; it < IN_IT; it++) {
            int idx = tid + it * 256;
            if (idx < IN_ELEMS) {
                int icl = idx / ((ATY+2)*(ATX+2));
                int rem = idx % ((ATY+2)*(ATX+2));
                int py  = rem / (ATX+2);
                int px  = rem % (ATX+2);
                sIn2[icl][py][px] = make_float2(inv[it], inv[it]);
            }
        }
#pragma unroll
        for (int it = 0; it < W_IT; it++) {
            int idx = tid + it * 256;
            sW[idx % 72][idx / 72] = wv[it];
        }
        __syncthreads();

        int chn = ch + ICC;
        if (chn < CIN) {
#pragma unroll
            for (int it = 0; it < IN_IT; it++) {
                int idx = tid + it * 256;
                float v = 0.f;
                if (idx < IN_ELEMS) {
                    int icl = idx / ((ATY+2)*(ATX+2));
                    int rem = idx % ((ATY+2)*(ATX+2));
                    int py  = rem / (ATX+2);
                    int px  = rem % (ATX+2);
                    int gy = y0 - 1 + py;
                    int gx = x0 - 1 + px;
                    int ic = chn + icl;
                    if (gy >= 0 && gy < H && gx >= 0 && gx < W) {
                        const float* src = (ic < C) ? (in0 + (size_t)ic * HW)
                                                    : (in1 + (size_t)(ic - C) * HW);
                        v = src[gy * W + gx];
                    }
                }
                inv[it] = v;
            }
#pragma unroll
            for (int it = 0; it < W_IT; it++) {
                int idx = tid + it * 256;
                int oc = idx / 72;
                int ks = idx % 72;
                int ocg = ocb * OCT + oc;
                float v = 0.f;
                if (ocg < NOFF)      v = off_w [(size_t)ocg * CIN * 9 + (size_t)chn * 9 + ks];
                else if (ocg < NOC)  v = mask_w[(size_t)(ocg - NOFF) * CIN * 9 + (size_t)chn * 9 + ks];
                wv[it] = v;
            }
        }

#pragma unroll
        for (int icl = 0; icl < ICC; icl++) {
            unsigned long long rv[3][6];
#pragma unroll
            for (int rr = 0; rr < 3; rr++) {
                const ulonglong2* rp =
                    reinterpret_cast<const ulonglong2*>(&sIn2[icl][r + rr][cq]);
                ulonglong2 u0 = rp[0], u1 = rp[1], u2 = rp[2];
                rv[rr][0] = u0.x; rv[rr][1] = u0.y;
                rv[rr][2] = u1.x; rv[rr][3] = u1.y;
                rv[rr][4] = u2.x; rv[rr][5] = u2.y;
            }
#pragma unroll
            for (int kk = 0; kk < 9; kk++) {
                const int ki = kk / 3, kj = kk % 3;
                const ulonglong2* wp =
                    reinterpret_cast<const ulonglong2*>(&sW[icl*9 + kk][oc_t*8]);
                ulonglong2 wA = wp[0];
                ulonglong2 wB = wp[1];
#pragma unroll
                for (int px = 0; px < 4; px++) {
                    unsigned long long A = rv[ki][kj + px];
                    FMA_F32X2(acc[px][0], A, wA.x);
                    FMA_F32X2(acc[px][1], A, wA.y);
                    FMA_F32X2(acc[px][2], A, wB.x);
                    FMA_F32X2(acc[px][3], A, wB.y);
                }
            }
        }
    }

    {
        int gy = y0 + r;
        int gx = x0 + cq;
#pragma unroll
        for (int jp = 0; jp < 4; jp++) {
#pragma unroll
            for (int h = 0; h < 2; h++) {
                int ocg = ocb * OCT + oc_t * 8 + jp * 2 + h;
                if (ocg < NOC) {
                    float bv = (ocg < NOFF) ? off_b[ocg] : mask_b[ocg - NOFF];
                    float4 v;
                    float2 f0 = *reinterpret_cast<float2*>(&acc[0][jp]);
                    float2 f1 = *reinterpret_cast<float2*>(&acc[1][jp]);
                    float2 f2 = *reinterpret_cast<float2*>(&acc[2][jp]);
                    float2 f3 = *reinterpret_cast<float2*>(&acc[3][jp]);
                    v.x = ((h == 0) ? f0.x : f0.y) + bv;
                    v.y = ((h == 0) ? f1.x : f1.y) + bv;
                    v.z = ((h == 0) ? f2.x : f2.y) + bv;
                    v.w = ((h == 0) ? f3.x : f3.y) + bv;
                    *reinterpret_cast<float4*>(
                        &g_scr[((size_t)(b * NOC + ocg) * H + gy) * W + gx]) = v;
                }
            }
        }
    }
}

// ---------------------------------------------------------------------------
// Kernel B: R4 shape (16 px, 128 threads, full-K smem A) with
//  - vectorized gathers from g_tr (2x LDG.128 per tap)
//  - K-dim permuted to g*72 + k*8 + c  -> contiguous STS.128 phase-1 writes
//  - weights staged in the same permuted order, group-sized chunks (KC=72)
// Dynamic smem: sA[16*580] + sWt[72*68] = 56704 B
// ---------------------------------------------------------------------------
#define TPX 16
#define KTOT 576
#define ASTR 580    // multiple of 4 (STS.128 alignment), 580%32=4 -> phase-clean
#define WSTR 68

extern __shared__ float smemB[];

__global__ __launch_bounds__(128) void kernB(const float* __restrict__ weight,
                                             const float* __restrict__ bias,
                                             float* __restrict__ out)
{
    float* sA  = smemB;                  // [16][580]
    float* sWt = smemB + TPX * ASTR;     // [72][68]

    const int bx = blockIdx.x;           // W/16
    const int y  = blockIdx.y;           // H
    const int b  = blockIdx.z;           // B
    const int x0 = bx * TPX;
    const int tid = threadIdx.x;

    const float* scr = g_scr + (size_t)b * NOC * HW;

    // ---- phase 1: sampled*mask -> sA[p][g*72 + k*8 + c] ----
    for (int task = tid; task < TPX * 72; task += 128) {
        int p  = task & (TPX - 1);       // pixel minor -> coalesced
        int gk = task >> 4;              // 0..71
        int g  = gk / 9;
        int k  = gk - g * 9;
        int x  = x0 + p;
        int base = y * W + x;

        float dy = scr[(size_t)(2*gk)      * HW + base];
        float dx = scr[(size_t)(2*gk + 1)  * HW + base];
        float mr = scr[(size_t)(NOFF + gk) * HW + base];
        float m  = 1.f / (1.f + __expf(-mr));

        float ys = dy + (float)(y - 1 + k / 3);
        float xs = dx + (float)(x - 1 + k % 3);
        float yf = floorf(ys), xf = floorf(xs);
        float wy = ys - yf,    wx = xs - xf;
        int yi = (int)yf, xi = (int)xf;

        bool vy0 = (yi >= 0) && (yi < H);
        bool vy1 = (yi + 1 >= 0) && (yi + 1 < H);
        bool vx0 = (xi >= 0) && (xi < W);
        bool vx1 = (xi + 1 >= 0) && (xi + 1 < W);

        float w00 = ((vy0 && vx0) ? (1.f - wy) * (1.f - wx) : 0.f) * m;
        float w01 = ((vy0 && vx1) ? (1.f - wy) * wx         : 0.f) * m;
        float w10 = ((vy1 && vx0) ? wy * (1.f - wx)         : 0.f) * m;
        float w11 = ((vy1 && vx1) ? wy * wx                 : 0.f) * m;

        int yc0 = min(max(yi,     0), H - 1);
        int yc1 = min(max(yi + 1, 0), H - 1);
        int xc0 = min(max(xi,     0), W - 1);
        int xc1 = min(max(xi + 1, 0), W - 1);

        const float* gb = g_tr + (size_t)(b * DG + g) * HW * CG;
        const float4* t00 = reinterpret_cast<const float4*>(gb + (size_t)(yc0 * W + xc0) * CG);
        const float4* t01 = reinterpret_cast<const float4*>(gb + (size_t)(yc0 * W + xc1) * CG);
        const float4* t10 = reinterpret_cast<const float4*>(gb + (size_t)(yc1 * W + xc0) * CG);
        const float4* t11 = reinterpret_cast<const float4*>(gb + (size_t)(yc1 * W + xc1) * CG);

        float4 a00 = __ldg(t00),     b00 = __ldg(t00 + 1);
        float4 a01 = __ldg(t01),     b01 = __ldg(t01 + 1);
        float4 a10 = __ldg(t10),     b10 = __ldg(t10 + 1);
        float4 a11 = __ldg(t11),     b11 = __ldg(t11 + 1);

        float4 ra, rb;
        ra.x = w00*a00.x + w01*a01.x + w10*a10.x + w11*a11.x;
        ra.y = w00*a00.y + w01*a01.y + w10*a10.y + w11*a11.y;
        ra.z = w00*a00.z + w01*a01.z + w10*a10.z + w11*a11.z;
        ra.w = w00*a00.w + w01*a01.w + w10*a10.w + w11*a11.w;
        rb.x = w00*b00.x + w01*b01.x + w10*b10.x + w11*b11.x;
        rb.y = w00*b00.y + w01*b01.y + w10*b10.y + w11*b11.y;
        rb.z = w00*b00.z + w01*b01.z + w10*b10.z + w11*b11.z;
        rb.w = w00*b00.w + w01*b01.w + w10*b10.w + w11*b11.w;

        float* dst = &sA[p * ASTR + g * 72 + k * 8];
        *reinterpret_cast<float4*>(dst)     = ra;
        *reinterpret_cast<float4*>(dst + 4) = rb;
    }
    __syncthreads();

    // ---- phase 2: out[p][o] = sum_kl sA[p][kl] * sWt[kl][o], per group ----
    const int oc_t = tid & 15;   // 16 groups x 4 oc
    const int px_t = tid >> 4;   // 8 -> handles px_t and px_t+8
    unsigned long long acc[2][2];
#pragma unroll
    for (int i = 0; i < 2; i++)
#pragma unroll
        for (int j = 0; j < 2; j++) acc[i][j] = 0ull;

    for (int g = 0; g < DG; g++) {
        // stage permuted weight slice: sWt[k*8+c][o] = weight[o][(g*8+c)*9+k]
        for (int idx = tid; idx < 72 * 64; idx += 128) {
            int o  = idx / 72;
            int kl = idx % 72;
            int k  = kl >> 3;
            int c  = kl & 7;
            sWt[kl * WSTR + o] = weight[(size_t)o * KTOT + (size_t)(g * CG + c) * 9 + k];
        }
        __syncthreads();
#pragma unroll 8
        for (int kl = 0; kl < 72; kl++) {
            float a0 = sA[px_t * ASTR + g * 72 + kl];
            float a1 = sA[(px_t + 8) * ASTR + g * 72 + kl];
            unsigned long long A0, A1;
            PACK2(A0, a0, a0);
            PACK2(A1, a1, a1);
            ulonglong2 wv = *reinterpret_cast<const ulonglong2*>(&sWt[kl * WSTR + oc_t * 4]);
            FMA_F32X2(acc[0][0], A0, wv.x);
            FMA_F32X2(acc[0][1], A0, wv.y);
            FMA_F32X2(acc[1][0], A1, wv.x);
            FMA_F32X2(acc[1][1], A1, wv.y);
        }
        __syncthreads();
    }

    // ---- store + bias ----
#pragma unroll
    for (int i = 0; i < 2; i++) {
        int p = px_t + i * 8;
        int x = x0 + p;
#pragma unroll
        for (int jp = 0; jp < 2; jp++) {
            float2 f = *reinterpret_cast<float2*>(&acc[i][jp]);
#pragma unroll
            for (int h = 0; h < 2; h++) {
                int o = oc_t * 4 + jp * 2 + h;
                float v = (h == 0) ? f.x : f.y;
                out[((size_t)(b * C + o) * H + y) * W + x] = v + bias[o];
            }
        }
    }
}

// ---------------------------------------------------------------------------
extern "C" void kernel_launch(void* const* d_in, const int* in_sizes, int n_in,
                              void* d_out, int out_size) {
    const float* ref    = (const float*)d_in[0];
    const float* nbr    = (const float*)d_in[1];
    const float* off_w  = (const float*)d_in[2];
    const float* off_b  = (const float*)d_in[3];
    const float* mask_w = (const float*)d_in[4];
    const float* mask_b = (const float*)d_in[5];
    const float* weight = (const float*)d_in[6];
    const float* bias   = (const float*)d_in[7];
    float* out = (float*)d_out;

    static int smem_set = 0;
    const int kb_smem = (TPX * ASTR + 72 * WSTR) * 4;   // 56704 B
    if (!smem_set) {
        cudaFuncSetAttribute(kernB, cudaFuncAttributeMaxDynamicSharedMemorySize, kb_smem);
        smem_set = 1;
    }

    dim3 gT(W / 32, H, BB);
    transp<<<gT, 256>>>(nbr);

    dim3 gA(W / ATX, H / ATY, BB * OCB_COUNT);
    convA<<<gA, 256>>>(ref, nbr, off_w, off_b, mask_w, mask_b);

    dim3 gB(W / TPX, H, BB);
    kernB<<<gB, 128, kb_smem>>>(weight, bias, out);
}

// round 10
// speedup vs baseline: 2.3053x; 1.5582x over previous
#include <cuda_runtime.h>
#include <cuda_bf16.h>
#include <math.h>
#include <stdint.h>

#define BB  2
#define C   64
#define H   256
#define W   256
#define HW  (H*W)
#define KK  9
#define DG  8
#define CG  8
#define CIN 128
#define NOFF 144
#define NMSK 72
#define NOC  216

// Packed fp32x2 FMA (Blackwell).
#define FMA_F32X2(acc, a, b) \
    asm("fma.rn.f32x2 %0, %1, %2, %0;" : "+l"(acc) : "l"(a), "l"(b))
#define PACK2(out, lo, hi) \
    asm("mov.b64 %0, {%1, %2};" : "=l"(out) : "f"(lo), "f"(hi))

// Warp-level bf16 MMA (portable: sm_80+, valid on compute_103).
#define MMA_BF16(c0, c1, c2, c3, a0, a1, a2, a3, b0, b1) \
    asm volatile("mma.sync.aligned.m16n8k16.row.col.f32.bf16.bf16.f32 " \
        "{%0,%1,%2,%3}, {%4,%5,%6,%7}, {%8,%9}, {%0,%1,%2,%3};" \
        : "+f"(c0), "+f"(c1), "+f"(c2), "+f"(c3) \
        : "r"(a0), "r"(a1), "r"(a2), "r"(a3), "r"(b0), "r"(b1))

// ---------------- globals ----------------
__device__ float g_scr[BB * NOC * H * W];                // conv out [b][216][y][x]
__device__ float g_tr[BB * DG * H * W * CG];             // nbr NHWC per group
__device__ __nv_bfloat16 g_bpan[2][18][NOC * 64];        // B panels [hi/lo][chunk][n][k64]

// ---------------------------------------------------------------------------
// transp: nbr [b][c][y][x] -> g_tr [b][g][y][x][c8]
// ---------------------------------------------------------------------------
__global__ __launch_bounds__(256) void transp(const float* __restrict__ nbr)
{
    const int x  = blockIdx.x * 32 + (threadIdx.x & 31);
    const int gi = threadIdx.x >> 5;
    const int y  = blockIdx.y;
    const int b  = blockIdx.z;

    const float* src = nbr + ((size_t)(b * C + gi * CG) * HW) + y * W + x;
    float4 a, q;
    a.x = src[0];            a.y = src[(size_t)HW];
    a.z = src[2*(size_t)HW]; a.w = src[3*(size_t)HW];
    q.x = src[4*(size_t)HW]; q.y = src[5*(size_t)HW];
    q.z = src[6*(size_t)HW]; q.w = src[7*(size_t)HW];

    float* dst = g_tr + ((size_t)(b * DG + gi) * HW + y * W + x) * CG;
    *reinterpret_cast<float4*>(dst)     = a;
    *reinterpret_cast<float4*>(dst + 4) = q;
}

// ---------------------------------------------------------------------------
// prepW: weights -> bf16 hi/lo B panels, plain layout [chunk][n][k64].
// K order: K = kk*128 + ch; chunk c: kk = c>>1, ch = (c&1)*64 + col.
// ---------------------------------------------------------------------------
__global__ void prepW(const float* __restrict__ off_w,
                      const float* __restrict__ mask_w)
{
    const int n   = blockIdx.x;      // 0..215 (out channel)
    const int c   = blockIdx.y;      // 0..17  (K chunk)
    const int col = threadIdx.x;     // 0..63  (k within chunk)
    const int kk  = c >> 1;
    const int ch  = (c & 1) * 64 + col;

    float w;
    if (n < NOFF) w = off_w [(size_t)n * CIN * 9 + ch * 9 + kk];
    else          w = mask_w[(size_t)(n - NOFF) * CIN * 9 + ch * 9 + kk];

    __nv_bfloat16 hi = __float2bfloat16(w);
    __nv_bfloat16 lo = __float2bfloat16(w - __bfloat162float(hi));

    g_bpan[0][c][n * 64 + col] = hi;
    g_bpan[1][c][n * 64 + col] = lo;
}

// ---------------------------------------------------------------------------
// convA_mma: offset+mask conv as warp-MMA bf16 split GEMM.
// Block tile: M=128 px (8 rows x 16 cols), N=216, K=1152 (18 chunks of 64).
// 256 threads = 8 warps; warp w owns px rows [w*16, w*16+16), all 27 n-tiles.
// smem (bf16, stride 72 = 36 words -> conflict-free fragment LDS):
//   sAh[128][72], sAl[128][72], sBh[216][72], sBl[216][72]  = 99072 B
// ---------------------------------------------------------------------------
#define ASTRIDE 72
#define OFF_AH  0
#define OFF_AL  (128 * ASTRIDE)
#define OFF_BH  (2 * 128 * ASTRIDE)
#define OFF_BL  (2 * 128 * ASTRIDE + NOC * ASTRIDE)
#define CMA_SMEM ((2 * 128 * ASTRIDE + 2 * NOC * ASTRIDE) * 2)  // 99072 B

extern __shared__ __align__(16) __nv_bfloat16 smemM[];

__global__ __launch_bounds__(256)
void convA_mma(const float* __restrict__ ref,
               const float* __restrict__ nbr,
               const float* __restrict__ off_b,
               const float* __restrict__ mask_b)
{
    const int tid  = threadIdx.x;
    const int warp = tid >> 5;
    const int lane = tid & 31;
    const int g    = lane >> 2;      // 0..7
    const int t    = lane & 3;       // 0..3
    const int x0 = blockIdx.x * 16;
    const int y0 = blockIdx.y * 8;
    const int b  = blockIdx.z;
    const int px_base = warp * 16;

    float acc[27][4];
#pragma unroll
    for (int j = 0; j < 27; j++)
#pragma unroll
        for (int q = 0; q < 4; q++) acc[j][q] = 0.f;

    const float* img[2] = { ref + (size_t)b * C * HW, nbr + (size_t)b * C * HW };

    for (int c = 0; c < 18; c++) {
        const int kk  = c >> 1;
        const int dy_ = kk / 3 - 1;
        const int dx_ = kk % 3 - 1;
        const float* src = img[c & 1];

        __syncthreads();   // previous chunk's compute done reading smem

        // ---- stage B panels: g_bpan[hl][c][n][64] -> sB[n][72] ----
        for (int i = tid; i < 2 * NOC * 8; i += 256) {
            int hl = i >= NOC * 8;
            int r  = hl ? (i - NOC * 8) : i;
            int n  = r >> 3;
            int u  = r & 7;
            const uint4 v = __ldg(reinterpret_cast<const uint4*>(
                &g_bpan[hl][c][n * 64 + u * 8]));
            *reinterpret_cast<uint4*>(
                &smemM[(hl ? OFF_BL : OFF_BH) + n * ASTRIDE + u * 8]) = v;
        }

        // ---- build A panels: shifted 8x16 window of 64 channels ----
        {
            const int px = tid & 127;
            const int cp = (tid >> 7) * 2;     // 0 or 2
            const int yy = y0 + (px >> 4) + dy_;
            const int xx = x0 + (px & 15) + dx_;
            const bool v = (yy >= 0) && (yy < H) && (xx >= 0) && (xx < W);
            const int off = yy * W + xx;
#pragma unroll
            for (int i = 0; i < 16; i++) {
                const int ch = i * 4 + cp;     // covers 0..63
                float f0 = 0.f, f1 = 0.f;
                if (v) {
                    f0 = __ldg(src + (size_t)ch * HW + off);
                    f1 = __ldg(src + (size_t)(ch + 1) * HW + off);
                }
                __nv_bfloat162 h2 = __float22bfloat162_rn(make_float2(f0, f1));
                float r0 = f0 - __bfloat162float(h2.x);
                float r1 = f1 - __bfloat162float(h2.y);
                __nv_bfloat162 l2 = __float22bfloat162_rn(make_float2(r0, r1));
                *reinterpret_cast<uint32_t*>(&smemM[OFF_AH + px * ASTRIDE + ch]) =
                    *reinterpret_cast<uint32_t*>(&h2);
                *reinterpret_cast<uint32_t*>(&smemM[OFF_AL + px * ASTRIDE + ch]) =
                    *reinterpret_cast<uint32_t*>(&l2);
            }
        }
        __syncthreads();

        // ---- compute: 4 k-steps x 27 n-tiles x 3 split MMAs ----
#pragma unroll
        for (int ks = 0; ks < 4; ks++) {
            const int kb = ks * 16;
            const int ra = (px_base + g) * ASTRIDE + kb + t * 2;
            uint32_t ah0 = *reinterpret_cast<const uint32_t*>(&smemM[OFF_AH + ra]);
            uint32_t ah1 = *reinterpret_cast<const uint32_t*>(&smemM[OFF_AH + ra + 8 * ASTRIDE]);
            uint32_t ah2 = *reinterpret_cast<const uint32_t*>(&smemM[OFF_AH + ra + 8]);
            uint32_t ah3 = *reinterpret_cast<const uint32_t*>(&smemM[OFF_AH + ra + 8 * ASTRIDE + 8]);
            uint32_t al0 = *reinterpret_cast<const uint32_t*>(&smemM[OFF_AL + ra]);
            uint32_t al1 = *reinterpret_cast<const uint32_t*>(&smemM[OFF_AL + ra + 8 * ASTRIDE]);
            uint32_t al2 = *reinterpret_cast<const uint32_t*>(&smemM[OFF_AL + ra + 8]);
            uint32_t al3 = *reinterpret_cast<const uint32_t*>(&smemM[OFF_AL + ra + 8 * ASTRIDE + 8]);
#pragma unroll
            for (int j = 0; j < 27; j++) {
                const int rb = (j * 8 + g) * ASTRIDE + kb + t * 2;
                uint32_t bh0 = *reinterpret_cast<const uint32_t*>(&smemM[OFF_BH + rb]);
                uint32_t bh1 = *reinterpret_cast<const uint32_t*>(&smemM[OFF_BH + rb + 8]);
                uint32_t bl0 = *reinterpret_cast<const uint32_t*>(&smemM[OFF_BL + rb]);
                uint32_t bl1 = *reinterpret_cast<const uint32_t*>(&smemM[OFF_BL + rb + 8]);
                MMA_BF16(acc[j][0], acc[j][1], acc[j][2], acc[j][3],
                         ah0, ah1, ah2, ah3, bh0, bh1);
                MMA_BF16(acc[j][0], acc[j][1], acc[j][2], acc[j][3],
                         ah0, ah1, ah2, ah3, bl0, bl1);
                MMA_BF16(acc[j][0], acc[j][1], acc[j][2], acc[j][3],
                         al0, al1, al2, al3, bh0, bh1);
            }
        }
    }

    // ---- epilogue: fragment -> g_scr (+bias) ----
    // c0,c1: row g,   cols t*2, t*2+1 ; c2,c3: row g+8, same cols.
    const int gy = y0 + warp;           // px row within tile = warp
#pragma unroll
    for (int j = 0; j < 27; j++) {
        const int oc0 = j * 8 + t * 2;
        const int oc1 = oc0 + 1;
        const float bv0 = (oc0 < NOFF) ? __ldg(off_b + oc0) : __ldg(mask_b + oc0 - NOFF);
        const float bv1 = (oc1 < NOFF) ? __ldg(off_b + oc1) : __ldg(mask_b + oc1 - NOFF);
        const int xA = x0 + g;
        const int xB = x0 + g + 8;
        g_scr[((size_t)(b * NOC + oc0) * H + gy) * W + xA] = acc[j][0] + bv0;
        g_scr[((size_t)(b * NOC + oc1) * H + gy) * W + xA] = acc[j][1] + bv1;
        g_scr[((size_t)(b * NOC + oc0) * H + gy) * W + xB] = acc[j][2] + bv0;
        g_scr[((size_t)(b * NOC + oc1) * H + gy) * W + xB] = acc[j][3] + bv1;
    }
}

// ---------------------------------------------------------------------------
// Kernel B: unchanged from R7.
// ---------------------------------------------------------------------------
#define TPX 16
#define KTOT 576
#define ASTR 580
#define WSTR 68

extern __shared__ float smemB[];

__global__ __launch_bounds__(128) void kernB(const float* __restrict__ weight,
                                             const float* __restrict__ bias,
                                             float* __restrict__ out)
{
    float* sA  = smemB;
    float* sWt = smemB + TPX * ASTR;

    const int bx = blockIdx.x;
    const int y  = blockIdx.y;
    const int b  = blockIdx.z;
    const int x0 = bx * TPX;
    const int tid = threadIdx.x;

    const float* scr = g_scr + (size_t)b * NOC * HW;

    for (int task = tid; task < TPX * 72; task += 128) {
        int p  = task & (TPX - 1);
        int gk = task >> 4;
        int g  = gk / 9;
        int k  = gk - g * 9;
        int x  = x0 + p;
        int base = y * W + x;

        float dy = scr[(size_t)(2*gk)      * HW + base];
        float dx = scr[(size_t)(2*gk + 1)  * HW + base];
        float mr = scr[(size_t)(NOFF + gk) * HW + base];
        float m  = 1.f / (1.f + __expf(-mr));

        float ys = dy + (float)(y - 1 + k / 3);
        float xs = dx + (float)(x - 1 + k % 3);
        float yf = floorf(ys), xf = floorf(xs);
        float wy = ys - yf,    wx = xs - xf;
        int yi = (int)yf, xi = (int)xf;

        bool vy0 = (yi >= 0) && (yi < H);
        bool vy1 = (yi + 1 >= 0) && (yi + 1 < H);
        bool vx0 = (xi >= 0) && (xi < W);
        bool vx1 = (xi + 1 >= 0) && (xi + 1 < W);

        float w00 = ((vy0 && vx0) ? (1.f - wy) * (1.f - wx) : 0.f) * m;
        float w01 = ((vy0 && vx1) ? (1.f - wy) * wx         : 0.f) * m;
        float w10 = ((vy1 && vx0) ? wy * (1.f - wx)         : 0.f) * m;
        float w11 = ((vy1 && vx1) ? wy * wx                 : 0.f) * m;

        int yc0 = min(max(yi,     0), H - 1);
        int yc1 = min(max(yi + 1, 0), H - 1);
        int xc0 = min(max(xi,     0), W - 1);
        int xc1 = min(max(xi + 1, 0), W - 1);

        const float* gb = g_tr + (size_t)(b * DG + g) * HW * CG;
        const float4* t00 = reinterpret_cast<const float4*>(gb + (size_t)(yc0 * W + xc0) * CG);
        const float4* t01 = reinterpret_cast<const float4*>(gb + (size_t)(yc0 * W + xc1) * CG);
        const float4* t10 = reinterpret_cast<const float4*>(gb + (size_t)(yc1 * W + xc0) * CG);
        const float4* t11 = reinterpret_cast<const float4*>(gb + (size_t)(yc1 * W + xc1) * CG);

        float4 a00 = __ldg(t00),     b00 = __ldg(t00 + 1);
        float4 a01 = __ldg(t01),     b01 = __ldg(t01 + 1);
        float4 a10 = __ldg(t10),     b10 = __ldg(t10 + 1);
        float4 a11 = __ldg(t11),     b11 = __ldg(t11 + 1);

        float4 ra, rb;
        ra.x = w00*a00.x + w01*a01.x + w10*a10.x + w11*a11.x;
        ra.y = w00*a00.y + w01*a01.y + w10*a10.y + w11*a11.y;
        ra.z = w00*a00.z + w01*a01.z + w10*a10.z + w11*a11.z;
        ra.w = w00*a00.w + w01*a01.w + w10*a10.w + w11*a11.w;
        rb.x = w00*b00.x + w01*b01.x + w10*b10.x + w11*b11.x;
        rb.y = w00*b00.y + w01*b01.y + w10*b10.y + w11*b11.y;
        rb.z = w00*b00.z + w01*b01.z + w10*b10.z + w11*b11.z;
        rb.w = w00*b00.w + w01*b01.w + w10*b10.w + w11*b11.w;

        float* dst = &sA[p * ASTR + g * 72 + k * 8];
        *reinterpret_cast<float4*>(dst)     = ra;
        *reinterpret_cast<float4*>(dst + 4) = rb;
    }
    __syncthreads();

    const int oc_t = tid & 15;
    const int px_t = tid >> 4;
    unsigned long long acc[2][2];
#pragma unroll
    for (int i = 0; i < 2; i++)
#pragma unroll
        for (int j = 0; j < 2; j++) acc[i][j] = 0ull;

    for (int g = 0; g < DG; g++) {
        for (int idx = tid; idx < 72 * 64; idx += 128) {
            int o  = idx / 72;
            int kl = idx % 72;
            int k  = kl >> 3;
            int c  = kl & 7;
            sWt[kl * WSTR + o] = weight[(size_t)o * KTOT + (size_t)(g * CG + c) * 9 + k];
        }
        __syncthreads();
#pragma unroll 8
        for (int kl = 0; kl < 72; kl++) {
            float a0 = sA[px_t * ASTR + g * 72 + kl];
            float a1 = sA[(px_t + 8) * ASTR + g * 72 + kl];
            unsigned long long A0, A1;
            PACK2(A0, a0, a0);
            PACK2(A1, a1, a1);
            ulonglong2 wv = *reinterpret_cast<const ulonglong2*>(&sWt[kl * WSTR + oc_t * 4]);
            FMA_F32X2(acc[0][0], A0, wv.x);
            FMA_F32X2(acc[0][1], A0, wv.y);
            FMA_F32X2(acc[1][0], A1, wv.x);
            FMA_F32X2(acc[1][1], A1, wv.y);
        }
        __syncthreads();
    }

#pragma unroll
    for (int i = 0; i < 2; i++) {
        int p = px_t + i * 8;
        int x = x0 + p;
#pragma unroll
        for (int jp = 0; jp < 2; jp++) {
            float2 f = *reinterpret_cast<float2*>(&acc[i][jp]);
#pragma unroll
            for (int h = 0; h < 2; h++) {
                int o = oc_t * 4 + jp * 2 + h;
                float v = (h == 0) ? f.x : f.y;
                out[((size_t)(b * C + o) * H + y) * W + x] = v + bias[o];
            }
        }
    }
}

// ---------------------------------------------------------------------------
extern "C" void kernel_launch(void* const* d_in, const int* in_sizes, int n_in,
                              void* d_out, int out_size) {
    const float* ref    = (const float*)d_in[0];
    const float* nbr    = (const float*)d_in[1];
    const float* off_w  = (const float*)d_in[2];
    const float* off_b  = (const float*)d_in[3];
    const float* mask_w = (const float*)d_in[4];
    const float* mask_b = (const float*)d_in[5];
    const float* weight = (const float*)d_in[6];
    const float* bias   = (const float*)d_in[7];
    float* out = (float*)d_out;

    static int attr_set = 0;
    const int kb_smem = (TPX * ASTR + 72 * WSTR) * 4;
    if (!attr_set) {
        cudaFuncSetAttribute(kernB, cudaFuncAttributeMaxDynamicSharedMemorySize, kb_smem);
        cudaFuncSetAttribute(convA_mma, cudaFuncAttributeMaxDynamicSharedMemorySize, CMA_SMEM);
        attr_set = 1;
    }

    prepW<<<dim3(NOC, 18), 64>>>(off_w, mask_w);

    dim3 gT(W / 32, H, BB);
    transp<<<gT, 256>>>(nbr);

    dim3 gC(W / 16, H / 8, BB);
    convA_mma<<<gC, 256, CMA_SMEM>>>(ref, nbr, off_b, mask_b);

    dim3 gB(W / TPX, H, BB);
    kernB<<<gB, 128, kb_smem>>>(weight, bias, out);
}

// round 11
// speedup vs baseline: 4.0586x; 1.7605x over previous
#include <cuda_runtime.h>
#include <cuda_bf16.h>
#include <math.h>
#include <stdint.h>

#define BB  2
#define C   64
#define H   256
#define W   256
#define HW  (H*W)
#define KK  9
#define DG  8
#define CG  8
#define CIN 128
#define NOFF 144
#define NMSK 72
#define NOC  216

// Warp-level bf16 MMA (portable: sm_80+, valid on compute_103).
#define MMA_BF16(c0, c1, c2, c3, a0, a1, a2, a3, b0, b1) \
    asm volatile("mma.sync.aligned.m16n8k16.row.col.f32.bf16.bf16.f32 " \
        "{%0,%1,%2,%3}, {%4,%5,%6,%7}, {%8,%9}, {%0,%1,%2,%3};" \
        : "+f"(c0), "+f"(c1), "+f"(c2), "+f"(c3) \
        : "r"(a0), "r"(a1), "r"(a2), "r"(a3), "r"(b0), "r"(b1))

// ---------------- globals ----------------
__device__ float g_scr[BB * NOC * H * W];                // conv out [b][216][y][x]
__device__ float g_tr[BB * DG * H * W * CG];             // nbr NHWC per group
__device__ __nv_bfloat16 g_bpan[2][18][NOC * 64];        // convA B panels
__device__ uint2 g_wpan[2][8][36][32];                   // kernB B fragments
                                                         // [hl][ntile][kstep][lane]

// ---------------------------------------------------------------------------
// transp: nbr [b][c][y][x] -> g_tr [b][g][y][x][c8]
// ---------------------------------------------------------------------------
__global__ __launch_bounds__(256) void transp(const float* __restrict__ nbr)
{
    const int x  = blockIdx.x * 32 + (threadIdx.x & 31);
    const int gi = threadIdx.x >> 5;
    const int y  = blockIdx.y;
    const int b  = blockIdx.z;

    const float* src = nbr + ((size_t)(b * C + gi * CG) * HW) + y * W + x;
    float4 a, q;
    a.x = src[0];            a.y = src[(size_t)HW];
    a.z = src[2*(size_t)HW]; a.w = src[3*(size_t)HW];
    q.x = src[4*(size_t)HW]; q.y = src[5*(size_t)HW];
    q.z = src[6*(size_t)HW]; q.w = src[7*(size_t)HW];

    float* dst = g_tr + ((size_t)(b * DG + gi) * HW + y * W + x) * CG;
    *reinterpret_cast<float4*>(dst)     = a;
    *reinterpret_cast<float4*>(dst + 4) = q;
}

// ---------------------------------------------------------------------------
// prepW: offset/mask conv weights -> bf16 hi/lo panels for convA_mma.
// ---------------------------------------------------------------------------
__global__ void prepW(const float* __restrict__ off_w,
                      const float* __restrict__ mask_w)
{
    const int n   = blockIdx.x;
    const int c   = blockIdx.y;
    const int col = threadIdx.x;
    const int kk  = c >> 1;
    const int ch  = (c & 1) * 64 + col;

    float w;
    if (n < NOFF) w = off_w [(size_t)n * CIN * 9 + ch * 9 + kk];
    else          w = mask_w[(size_t)(n - NOFF) * CIN * 9 + ch * 9 + kk];

    __nv_bfloat16 hi = __float2bfloat16(w);
    __nv_bfloat16 lo = __float2bfloat16(w - __bfloat162float(hi));

    g_bpan[0][c][n * 64 + col] = hi;
    g_bpan[1][c][n * 64 + col] = lo;
}

// ---------------------------------------------------------------------------
// prepW2: main conv weight -> bf16 hi/lo fragments in exact m16n8k16 B order.
// K index kb = g*72 + k*8 + c  <->  weight[n][(g*8+c)*9 + k].
// Fragment (ntile j, kstep s): lane l (t=l&3, n=j*8+(l>>2)):
//   b0 = {B[n][16s+t*2], B[n][16s+t*2+1]},  b1 = {B[n][16s+t*2+8], +9}
// ---------------------------------------------------------------------------
__device__ __forceinline__ float wfetch(const float* w, int n, int kb) {
    int g = kb / 72, r = kb % 72, k = r >> 3, c = r & 7;
    return w[(size_t)n * 576 + (size_t)(g * CG + c) * 9 + k];
}

__global__ void prepW2(const float* __restrict__ weight)
{
    const int j = blockIdx.x;        // 0..7 ntile
    const int s = blockIdx.y;        // 0..35 kstep
    const int l = threadIdx.x;       // 0..31 lane
    const int t = l & 3;
    const int n = j * 8 + (l >> 2);

    float v[4];
    v[0] = wfetch(weight, n, s * 16 + t * 2);
    v[1] = wfetch(weight, n, s * 16 + t * 2 + 1);
    v[2] = wfetch(weight, n, s * 16 + t * 2 + 8);
    v[3] = wfetch(weight, n, s * 16 + t * 2 + 9);

    __nv_bfloat16 h[4], lo[4];
#pragma unroll
    for (int i = 0; i < 4; i++) {
        h[i]  = __float2bfloat16(v[i]);
        lo[i] = __float2bfloat16(v[i] - __bfloat162float(h[i]));
    }
    __nv_bfloat162 h01 = { h[0],  h[1] },  h23 = { h[2],  h[3] };
    __nv_bfloat162 l01 = { lo[0], lo[1] }, l23 = { lo[2], lo[3] };
    uint2 hv = { *reinterpret_cast<uint32_t*>(&h01), *reinterpret_cast<uint32_t*>(&h23) };
    uint2 lv = { *reinterpret_cast<uint32_t*>(&l01), *reinterpret_cast<uint32_t*>(&l23) };
    g_wpan[0][j][s][l] = hv;
    g_wpan[1][j][s][l] = lv;
}

// ---------------------------------------------------------------------------
// convA_mma: offset+mask conv as warp-MMA bf16 split GEMM (unchanged R10).
// ---------------------------------------------------------------------------
#define ASTRIDE 72
#define OFF_AH  0
#define OFF_AL  (128 * ASTRIDE)
#define OFF_BH  (2 * 128 * ASTRIDE)
#define OFF_BL  (2 * 128 * ASTRIDE + NOC * ASTRIDE)
#define CMA_SMEM ((2 * 128 * ASTRIDE + 2 * NOC * ASTRIDE) * 2)  // 99072 B

extern __shared__ __align__(16) __nv_bfloat16 smemM[];

__global__ __launch_bounds__(256)
void convA_mma(const float* __restrict__ ref,
               const float* __restrict__ nbr,
               const float* __restrict__ off_b,
               const float* __restrict__ mask_b)
{
    const int tid  = threadIdx.x;
    const int warp = tid >> 5;
    const int lane = tid & 31;
    const int g    = lane >> 2;
    const int t    = lane & 3;
    const int x0 = blockIdx.x * 16;
    const int y0 = blockIdx.y * 8;
    const int b  = blockIdx.z;
    const int px_base = warp * 16;

    float acc[27][4];
#pragma unroll
    for (int j = 0; j < 27; j++)
#pragma unroll
        for (int q = 0; q < 4; q++) acc[j][q] = 0.f;

    const float* img[2] = { ref + (size_t)b * C * HW, nbr + (size_t)b * C * HW };

    for (int c = 0; c < 18; c++) {
        const int kk  = c >> 1;
        const int dy_ = kk / 3 - 1;
        const int dx_ = kk % 3 - 1;
        const float* src = img[c & 1];

        __syncthreads();

        for (int i = tid; i < 2 * NOC * 8; i += 256) {
            int hl = i >= NOC * 8;
            int r  = hl ? (i - NOC * 8) : i;
            int n  = r >> 3;
            int u  = r & 7;
            const uint4 v = __ldg(reinterpret_cast<const uint4*>(
                &g_bpan[hl][c][n * 64 + u * 8]));
            *reinterpret_cast<uint4*>(
                &smemM[(hl ? OFF_BL : OFF_BH) + n * ASTRIDE + u * 8]) = v;
        }

        {
            const int px = tid & 127;
            const int cp = (tid >> 7) * 2;
            const int yy = y0 + (px >> 4) + dy_;
            const int xx = x0 + (px & 15) + dx_;
            const bool v = (yy >= 0) && (yy < H) && (xx >= 0) && (xx < W);
            const int off = yy * W + xx;
#pragma unroll
            for (int i = 0; i < 16; i++) {
                const int ch = i * 4 + cp;
                float f0 = 0.f, f1 = 0.f;
                if (v) {
                    f0 = __ldg(src + (size_t)ch * HW + off);
                    f1 = __ldg(src + (size_t)(ch + 1) * HW + off);
                }
                __nv_bfloat162 h2 = __float22bfloat162_rn(make_float2(f0, f1));
                float r0 = f0 - __bfloat162float(h2.x);
                float r1 = f1 - __bfloat162float(h2.y);
                __nv_bfloat162 l2 = __float22bfloat162_rn(make_float2(r0, r1));
                *reinterpret_cast<uint32_t*>(&smemM[OFF_AH + px * ASTRIDE + ch]) =
                    *reinterpret_cast<uint32_t*>(&h2);
                *reinterpret_cast<uint32_t*>(&smemM[OFF_AL + px * ASTRIDE + ch]) =
                    *reinterpret_cast<uint32_t*>(&l2);
            }
        }
        __syncthreads();

#pragma unroll
        for (int ks = 0; ks < 4; ks++) {
            const int kb = ks * 16;
            const int ra = (px_base + g) * ASTRIDE + kb + t * 2;
            uint32_t ah0 = *reinterpret_cast<const uint32_t*>(&smemM[OFF_AH + ra]);
            uint32_t ah1 = *reinterpret_cast<const uint32_t*>(&smemM[OFF_AH + ra + 8 * ASTRIDE]);
            uint32_t ah2 = *reinterpret_cast<const uint32_t*>(&smemM[OFF_AH + ra + 8]);
            uint32_t ah3 = *reinterpret_cast<const uint32_t*>(&smemM[OFF_AH + ra + 8 * ASTRIDE + 8]);
            uint32_t al0 = *reinterpret_cast<const uint32_t*>(&smemM[OFF_AL + ra]);
            uint32_t al1 = *reinterpret_cast<const uint32_t*>(&smemM[OFF_AL + ra + 8 * ASTRIDE]);
            uint32_t al2 = *reinterpret_cast<const uint32_t*>(&smemM[OFF_AL + ra + 8]);
            uint32_t al3 = *reinterpret_cast<const uint32_t*>(&smemM[OFF_AL + ra + 8 * ASTRIDE + 8]);
#pragma unroll
            for (int j = 0; j < 27; j++) {
                const int rb = (j * 8 + g) * ASTRIDE + kb + t * 2;
                uint32_t bh0 = *reinterpret_cast<const uint32_t*>(&smemM[OFF_BH + rb]);
                uint32_t bh1 = *reinterpret_cast<const uint32_t*>(&smemM[OFF_BH + rb + 8]);
                uint32_t bl0 = *reinterpret_cast<const uint32_t*>(&smemM[OFF_BL + rb]);
                uint32_t bl1 = *reinterpret_cast<const uint32_t*>(&smemM[OFF_BL + rb + 8]);
                MMA_BF16(acc[j][0], acc[j][1], acc[j][2], acc[j][3],
                         ah0, ah1, ah2, ah3, bh0, bh1);
                MMA_BF16(acc[j][0], acc[j][1], acc[j][2], acc[j][3],
                         ah0, ah1, ah2, ah3, bl0, bl1);
                MMA_BF16(acc[j][0], acc[j][1], acc[j][2], acc[j][3],
                         al0, al1, al2, al3, bh0, bh1);
            }
        }
    }

    const int gy = y0 + warp;
#pragma unroll
    for (int j = 0; j < 27; j++) {
        const int oc0 = j * 8 + t * 2;
        const int oc1 = oc0 + 1;
        const float bv0 = (oc0 < NOFF) ? __ldg(off_b + oc0) : __ldg(mask_b + oc0 - NOFF);
        const float bv1 = (oc1 < NOFF) ? __ldg(off_b + oc1) : __ldg(mask_b + oc1 - NOFF);
        const int xA = x0 + g;
        const int xB = x0 + g + 8;
        g_scr[((size_t)(b * NOC + oc0) * H + gy) * W + xA] = acc[j][0] + bv0;
        g_scr[((size_t)(b * NOC + oc1) * H + gy) * W + xA] = acc[j][1] + bv1;
        g_scr[((size_t)(b * NOC + oc0) * H + gy) * W + xB] = acc[j][2] + bv0;
        g_scr[((size_t)(b * NOC + oc1) * H + gy) * W + xB] = acc[j][3] + bv1;
    }
}

// ---------------------------------------------------------------------------
// Kernel B: phase 1 samples into bf16 hi/lo smem panels; phase 2 is warp-MMA
// bf16 split GEMM with B fragments streamed from g_wpan (no weight smem).
// Block: 16 px of one row, 128 threads (4 warps; warp w -> oc [w*16, w*16+16)).
// smem: sAh[16][584] + sAl[16][584] bf16 = 37376 B -> 6 blocks/SM.
// ---------------------------------------------------------------------------
#define TPX 16
#define SASTR 584     // bf16 elements per row (292 words -> conflict-free frags)

extern __shared__ __align__(16) __nv_bfloat16 smemB2[];

__global__ __launch_bounds__(128) void kernB(const float* __restrict__ bias,
                                             float* __restrict__ out)
{
    __nv_bfloat16* sAh = smemB2;
    __nv_bfloat16* sAl = smemB2 + TPX * SASTR;

    const int bx = blockIdx.x;           // W/16
    const int y  = blockIdx.y;           // H
    const int b  = blockIdx.z;           // B
    const int x0 = bx * TPX;
    const int tid = threadIdx.x;

    const float* scr = g_scr + (size_t)b * NOC * HW;

    // ---- phase 1: sample + mask (fp32), split hi/lo -> smem ----
    for (int task = tid; task < TPX * 72; task += 128) {
        int p  = task & (TPX - 1);
        int gk = task >> 4;
        int g  = gk / 9;
        int k  = gk - g * 9;
        int x  = x0 + p;
        int base = y * W + x;

        float dy = scr[(size_t)(2*gk)      * HW + base];
        float dx = scr[(size_t)(2*gk + 1)  * HW + base];
        float mr = scr[(size_t)(NOFF + gk) * HW + base];
        float m  = 1.f / (1.f + __expf(-mr));

        float ys = dy + (float)(y - 1 + k / 3);
        float xs = dx + (float)(x - 1 + k % 3);
        float yf = floorf(ys), xf = floorf(xs);
        float wy = ys - yf,    wx = xs - xf;
        int yi = (int)yf, xi = (int)xf;

        bool vy0 = (yi >= 0) && (yi < H);
        bool vy1 = (yi + 1 >= 0) && (yi + 1 < H);
        bool vx0 = (xi >= 0) && (xi < W);
        bool vx1 = (xi + 1 >= 0) && (xi + 1 < W);

        float w00 = ((vy0 && vx0) ? (1.f - wy) * (1.f - wx) : 0.f) * m;
        float w01 = ((vy0 && vx1) ? (1.f - wy) * wx         : 0.f) * m;
        float w10 = ((vy1 && vx0) ? wy * (1.f - wx)         : 0.f) * m;
        float w11 = ((vy1 && vx1) ? wy * wx                 : 0.f) * m;

        int yc0 = min(max(yi,     0), H - 1);
        int yc1 = min(max(yi + 1, 0), H - 1);
        int xc0 = min(max(xi,     0), W - 1);
        int xc1 = min(max(xi + 1, 0), W - 1);

        const float* gb = g_tr + (size_t)(b * DG + g) * HW * CG;
        const float4* t00 = reinterpret_cast<const float4*>(gb + (size_t)(yc0 * W + xc0) * CG);
        const float4* t01 = reinterpret_cast<const float4*>(gb + (size_t)(yc0 * W + xc1) * CG);
        const float4* t10 = reinterpret_cast<const float4*>(gb + (size_t)(yc1 * W + xc0) * CG);
        const float4* t11 = reinterpret_cast<const float4*>(gb + (size_t)(yc1 * W + xc1) * CG);

        float4 a00 = __ldg(t00),     b00 = __ldg(t00 + 1);
        float4 a01 = __ldg(t01),     b01 = __ldg(t01 + 1);
        float4 a10 = __ldg(t10),     b10 = __ldg(t10 + 1);
        float4 a11 = __ldg(t11),     b11 = __ldg(t11 + 1);

        float v[8];
        v[0] = w00*a00.x + w01*a01.x + w10*a10.x + w11*a11.x;
        v[1] = w00*a00.y + w01*a01.y + w10*a10.y + w11*a11.y;
        v[2] = w00*a00.z + w01*a01.z + w10*a10.z + w11*a11.z;
        v[3] = w00*a00.w + w01*a01.w + w10*a10.w + w11*a11.w;
        v[4] = w00*b00.x + w01*b01.x + w10*b10.x + w11*b11.x;
        v[5] = w00*b00.y + w01*b01.y + w10*b10.y + w11*b11.y;
        v[6] = w00*b00.z + w01*b01.z + w10*b10.z + w11*b11.z;
        v[7] = w00*b00.w + w01*b01.w + w10*b10.w + w11*b11.w;

        uint32_t hw_[4], lw_[4];
#pragma unroll
        for (int i = 0; i < 4; i++) {
            __nv_bfloat162 h2 = __float22bfloat162_rn(make_float2(v[2*i], v[2*i+1]));
            float r0 = v[2*i]   - __bfloat162float(h2.x);
            float r1 = v[2*i+1] - __bfloat162float(h2.y);
            __nv_bfloat162 l2 = __float22bfloat162_rn(make_float2(r0, r1));
            hw_[i] = *reinterpret_cast<uint32_t*>(&h2);
            lw_[i] = *reinterpret_cast<uint32_t*>(&l2);
        }
        const int el = p * SASTR + g * 72 + k * 8;
        *reinterpret_cast<uint4*>(&sAh[el]) = make_uint4(hw_[0], hw_[1], hw_[2], hw_[3]);
        *reinterpret_cast<uint4*>(&sAl[el]) = make_uint4(lw_[0], lw_[1], lw_[2], lw_[3]);
    }
    __syncthreads();

    // ---- phase 2: warp-MMA. warp w -> ntiles {2w, 2w+1}; K = 576 = 36*16 ----
    const int warp = tid >> 5;
    const int lane = tid & 31;
    const int t    = lane & 3;
    const int gl   = lane >> 2;

    float acc[2][4];
#pragma unroll
    for (int jj = 0; jj < 2; jj++)
#pragma unroll
        for (int q = 0; q < 4; q++) acc[jj][q] = 0.f;

#pragma unroll 4
    for (int s = 0; s < 36; s++) {
        const int ra = gl * SASTR + s * 16 + t * 2;
        uint32_t ah0 = *reinterpret_cast<const uint32_t*>(&sAh[ra]);
        uint32_t ah1 = *reinterpret_cast<const uint32_t*>(&sAh[ra + 8 * SASTR]);
        uint32_t ah2 = *reinterpret_cast<const uint32_t*>(&sAh[ra + 8]);
        uint32_t ah3 = *reinterpret_cast<const uint32_t*>(&sAh[ra + 8 * SASTR + 8]);
        uint32_t al0 = *reinterpret_cast<const uint32_t*>(&sAl[ra]);
        uint32_t al1 = *reinterpret_cast<const uint32_t*>(&sAl[ra + 8 * SASTR]);
        uint32_t al2 = *reinterpret_cast<const uint32_t*>(&sAl[ra + 8]);
        uint32_t al3 = *reinterpret_cast<const uint32_t*>(&sAl[ra + 8 * SASTR + 8]);
#pragma unroll
        for (int jj = 0; jj < 2; jj++) {
            const int j = warp * 2 + jj;
            uint2 bh = __ldg(&g_wpan[0][j][s][lane]);
            uint2 bl = __ldg(&g_wpan[1][j][s][lane]);
            MMA_BF16(acc[jj][0], acc[jj][1], acc[jj][2], acc[jj][3],
                     ah0, ah1, ah2, ah3, bh.x, bh.y);
            MMA_BF16(acc[jj][0], acc[jj][1], acc[jj][2], acc[jj][3],
                     ah0, ah1, ah2, ah3, bl.x, bl.y);
            MMA_BF16(acc[jj][0], acc[jj][1], acc[jj][2], acc[jj][3],
                     al0, al1, al2, al3, bh.x, bh.y);
        }
    }

    // ---- epilogue: fragment rows = px, cols = oc ----
#pragma unroll
    for (int jj = 0; jj < 2; jj++) {
        const int j = warp * 2 + jj;
        const int oc0 = j * 8 + t * 2;
        const int oc1 = oc0 + 1;
        const float bv0 = __ldg(bias + oc0);
        const float bv1 = __ldg(bias + oc1);
        const int xA = x0 + gl;
        const int xB = x0 + gl + 8;
        out[((size_t)(b * C + oc0) * H + y) * W + xA] = acc[jj][0] + bv0;
        out[((size_t)(b * C + oc1) * H + y) * W + xA] = acc[jj][1] + bv1;
        out[((size_t)(b * C + oc0) * H + y) * W + xB] = acc[jj][2] + bv0;
        out[((size_t)(b * C + oc1) * H + y) * W + xB] = acc[jj][3] + bv1;
    }
}

// ---------------------------------------------------------------------------
extern "C" void kernel_launch(void* const* d_in, const int* in_sizes, int n_in,
                              void* d_out, int out_size) {
    const float* ref    = (const float*)d_in[0];
    const float* nbr    = (const float*)d_in[1];
    const float* off_w  = (const float*)d_in[2];
    const float* off_b  = (const float*)d_in[3];
    const float* mask_w = (const float*)d_in[4];
    const float* mask_b = (const float*)d_in[5];
    const float* weight = (const float*)d_in[6];
    const float* bias   = (const float*)d_in[7];
    float* out = (float*)d_out;

    static int attr_set = 0;
    const int kb_smem = 2 * TPX * SASTR * 2;   // 37376 B
    if (!attr_set) {
        cudaFuncSetAttribute(convA_mma, cudaFuncAttributeMaxDynamicSharedMemorySize, CMA_SMEM);
        attr_set = 1;
    }

    prepW<<<dim3(NOC, 18), 64>>>(off_w, mask_w);
    prepW2<<<dim3(8, 36), 32>>>(weight);

    dim3 gT(W / 32, H, BB);
    transp<<<gT, 256>>>(nbr);

    dim3 gC(W / 16, H / 8, BB);
    convA_mma<<<gC, 256, CMA_SMEM>>>(ref, nbr, off_b, mask_b);

    dim3 gB(W / TPX, H, BB);
    kernB<<<gB, 128, kb_smem>>>(bias, out);
}

// round 12
// speedup vs baseline: 4.5372x; 1.1179x over previous
#include <cuda_runtime.h>
#include <cuda_bf16.h>
#include <math.h>
#include <stdint.h>

#define BB  2
#define C   64
#define H   256
#define W   256
#define HW  (H*W)
#define KK  9
#define DG  8
#define CG  8
#define CIN 128
#define NOFF 144
#define NMSK 72
#define NOC  216

// Warp-level bf16 MMA (portable: sm_80+, valid on compute_103).
#define MMA_BF16(c0, c1, c2, c3, a0, a1, a2, a3, b0, b1) \
    asm volatile("mma.sync.aligned.m16n8k16.row.col.f32.bf16.bf16.f32 " \
        "{%0,%1,%2,%3}, {%4,%5,%6,%7}, {%8,%9}, {%0,%1,%2,%3};" \
        : "+f"(c0), "+f"(c1), "+f"(c2), "+f"(c3) \
        : "r"(a0), "r"(a1), "r"(a2), "r"(a3), "r"(b0), "r"(b1))

#define CP_ASYNC16(smaddr, gptr) \
    asm volatile("cp.async.cg.shared.global [%0], [%1], 16;" \
                 :: "r"(smaddr), "l"(gptr) : "memory")
#define CP_COMMIT() asm volatile("cp.async.commit_group;" ::: "memory")
#define CP_WAIT(n)  asm volatile("cp.async.wait_group %0;" :: "n"(n) : "memory")

__device__ __forceinline__ uint32_t smem_u32(const void* p) {
    uint32_t a;
    asm("{ .reg .u64 t; cvta.to.shared.u64 t, %1; cvt.u32.u64 %0, t; }"
        : "=r"(a) : "l"(p));
    return a;
}

// split fp32 pair -> packed bf16x2 hi + lo(residual)
__device__ __forceinline__ void split2(float f0, float f1, uint32_t& h, uint32_t& l) {
    __nv_bfloat162 h2 = __float22bfloat162_rn(make_float2(f0, f1));
    float r0 = f0 - __bfloat162float(h2.x);
    float r1 = f1 - __bfloat162float(h2.y);
    __nv_bfloat162 l2 = __float22bfloat162_rn(make_float2(r0, r1));
    h = *reinterpret_cast<uint32_t*>(&h2);
    l = *reinterpret_cast<uint32_t*>(&l2);
}

// ---------------- globals ----------------
__device__ float g_scr[BB * NOC * H * W];                // conv out [b][216][y][x]
__device__ float g_tr[BB * DG * H * W * CG];             // nbr NHWC per group
__device__ __nv_bfloat16 g_bpan[2][18][NOC * 64];        // convA B panels
__device__ uint2 g_wpan[2][8][36][32];                   // kernB B fragments

// ---------------------------------------------------------------------------
// transp: nbr [b][c][y][x] -> g_tr [b][g][y][x][c8]
// ---------------------------------------------------------------------------
__global__ __launch_bounds__(256) void transp(const float* __restrict__ nbr)
{
    const int x  = blockIdx.x * 32 + (threadIdx.x & 31);
    const int gi = threadIdx.x >> 5;
    const int y  = blockIdx.y;
    const int b  = blockIdx.z;

    const float* src = nbr + ((size_t)(b * C + gi * CG) * HW) + y * W + x;
    float4 a, q;
    a.x = src[0];            a.y = src[(size_t)HW];
    a.z = src[2*(size_t)HW]; a.w = src[3*(size_t)HW];
    q.x = src[4*(size_t)HW]; q.y = src[5*(size_t)HW];
    q.z = src[6*(size_t)HW]; q.w = src[7*(size_t)HW];

    float* dst = g_tr + ((size_t)(b * DG + gi) * HW + y * W + x) * CG;
    *reinterpret_cast<float4*>(dst)     = a;
    *reinterpret_cast<float4*>(dst + 4) = q;
}

// ---------------------------------------------------------------------------
// prepW: offset/mask conv weights -> bf16 hi/lo panels for convA_mma.
// ---------------------------------------------------------------------------
__global__ void prepW(const float* __restrict__ off_w,
                      const float* __restrict__ mask_w)
{
    const int n   = blockIdx.x;
    const int c   = blockIdx.y;
    const int col = threadIdx.x;
    const int kk  = c >> 1;
    const int ch  = (c & 1) * 64 + col;

    float w;
    if (n < NOFF) w = off_w [(size_t)n * CIN * 9 + ch * 9 + kk];
    else          w = mask_w[(size_t)(n - NOFF) * CIN * 9 + ch * 9 + kk];

    __nv_bfloat16 hi = __float2bfloat16(w);
    __nv_bfloat16 lo = __float2bfloat16(w - __bfloat162float(hi));

    g_bpan[0][c][n * 64 + col] = hi;
    g_bpan[1][c][n * 64 + col] = lo;
}

// ---------------------------------------------------------------------------
// prepW2: main conv weight -> bf16 hi/lo fragments in m16n8k16 B order.
// ---------------------------------------------------------------------------
__device__ __forceinline__ float wfetch(const float* w, int n, int kb) {
    int g = kb / 72, r = kb % 72, k = r >> 3, c = r & 7;
    return w[(size_t)n * 576 + (size_t)(g * CG + c) * 9 + k];
}

__global__ void prepW2(const float* __restrict__ weight)
{
    const int j = blockIdx.x;
    const int s = blockIdx.y;
    const int l = threadIdx.x;
    const int t = l & 3;
    const int n = j * 8 + (l >> 2);

    float v[4];
    v[0] = wfetch(weight, n, s * 16 + t * 2);
    v[1] = wfetch(weight, n, s * 16 + t * 2 + 1);
    v[2] = wfetch(weight, n, s * 16 + t * 2 + 8);
    v[3] = wfetch(weight, n, s * 16 + t * 2 + 9);

    uint2 hv, lv;
    split2(v[0], v[1], hv.x, lv.x);
    split2(v[2], v[3], hv.y, lv.y);
    g_wpan[0][j][s][l] = hv;
    g_wpan[1][j][s][l] = lv;
}

// ---------------------------------------------------------------------------
// convA_mma: offset+mask conv, warp-MMA bf16 split GEMM.
// R12: A fragments loaded gmem->registers directly (no A smem);
//      B panels double-buffered via cp.async (staging overlaps compute).
// smem: sB[2 buf][2 hl][216][72] bf16 = 124416 B.
// ---------------------------------------------------------------------------
#define BSTRIDE 72
#define BUF_HALF (NOC * BSTRIDE)            // elements per hl panel (15552)
#define BUF_SIZE (2 * BUF_HALF)             // elements per buffer  (31104)
#define CMA_SMEM (2 * BUF_SIZE * 2)         // bytes: 124416

extern __shared__ __align__(16) __nv_bfloat16 smemM[];

__global__ __launch_bounds__(256)
void convA_mma(const float* __restrict__ ref,
               const float* __restrict__ nbr,
               const float* __restrict__ off_b,
               const float* __restrict__ mask_b)
{
    const int tid  = threadIdx.x;
    const int warp = tid >> 5;
    const int lane = tid & 31;
    const int g    = lane >> 2;
    const int t    = lane & 3;
    const int x0 = blockIdx.x * 16;
    const int y0 = blockIdx.y * 8;
    const int b  = blockIdx.z;

    const uint32_t sm_base = smem_u32(smemM);

    float acc[27][4];
#pragma unroll
    for (int j = 0; j < 27; j++)
#pragma unroll
        for (int q = 0; q < 4; q++) acc[j][q] = 0.f;

    const float* img[2] = { ref + (size_t)b * C * HW, nbr + (size_t)b * C * HW };

    // issue B staging for chunk `cc` into buffer `buf`
    auto issueB = [&](int cc, int buf) {
        const uint32_t dst0 = sm_base + buf * (BUF_SIZE * 2);
        for (int i = tid; i < 2 * NOC * 8; i += 256) {
            int hl = i >= NOC * 8;
            int r  = hl ? (i - NOC * 8) : i;
            int n  = r >> 3;
            int u  = r & 7;
            const __nv_bfloat16* src = &g_bpan[hl][cc][n * 64 + u * 8];
            uint32_t dst = dst0 + (uint32_t)(hl * BUF_HALF + n * BSTRIDE + u * 8) * 2;
            CP_ASYNC16(dst, src);
        }
    };

    issueB(0, 0);
    CP_COMMIT();

    for (int c = 0; c < 18; c++) {
        const int buf = c & 1;
        const int kk  = c >> 1;
        const int dy_ = kk / 3 - 1;
        const int dx_ = kk % 3 - 1;
        const float* src = img[c & 1];

        if (c + 1 < 18) {
            issueB(c + 1, buf ^ 1);
            CP_COMMIT();
            CP_WAIT(1);
        } else {
            CP_WAIT(0);
        }
        __syncthreads();   // chunk c's B panels visible to all threads

        // ---- A fragments: gmem -> registers ----
        // warp's m16 rows = pixels (y0+warp, x0+r), r = 0..15
        const int yy  = y0 + warp + dy_;
        const int xxA = x0 + g + dx_;
        const int xxB = xxA + 8;
        const bool okY = (yy >= 0) && (yy < H);
        const bool vA = okY && (xxA >= 0) && (xxA < W);
        const bool vB = okY && (xxB >= 0) && (xxB < W);
        const int oA = yy * W + xxA;
        const int oB = yy * W + xxB;

        uint32_t AH[4][4], AL[4][4];
#pragma unroll
        for (int ks = 0; ks < 4; ks++) {
            const int cb = ks * 16 + t * 2;
            float fA0 = vA ? __ldg(src + (size_t)cb * HW + oA) : 0.f;
            float fA1 = vA ? __ldg(src + (size_t)(cb + 1) * HW + oA) : 0.f;
            float fA2 = vA ? __ldg(src + (size_t)(cb + 8) * HW + oA) : 0.f;
            float fA3 = vA ? __ldg(src + (size_t)(cb + 9) * HW + oA) : 0.f;
            float fB0 = vB ? __ldg(src + (size_t)cb * HW + oB) : 0.f;
            float fB1 = vB ? __ldg(src + (size_t)(cb + 1) * HW + oB) : 0.f;
            float fB2 = vB ? __ldg(src + (size_t)(cb + 8) * HW + oB) : 0.f;
            float fB3 = vB ? __ldg(src + (size_t)(cb + 9) * HW + oB) : 0.f;
            split2(fA0, fA1, AH[ks][0], AL[ks][0]);   // row g,   k lo
            split2(fB0, fB1, AH[ks][1], AL[ks][1]);   // row g+8, k lo
            split2(fA2, fA3, AH[ks][2], AL[ks][2]);   // row g,   k hi
            split2(fB2, fB3, AH[ks][3], AL[ks][3]);   // row g+8, k hi
        }

        // ---- compute: 4 k-steps x 27 n-tiles x 3 split MMAs ----
        const __nv_bfloat16* sBh = smemM + buf * BUF_SIZE;
        const __nv_bfloat16* sBl = sBh + BUF_HALF;
#pragma unroll
        for (int ks = 0; ks < 4; ks++) {
            const int kb = ks * 16;
#pragma unroll
            for (int j = 0; j < 27; j++) {
                const int rb = (j * 8 + g) * BSTRIDE + kb + t * 2;
                uint32_t bh0 = *reinterpret_cast<const uint32_t*>(&sBh[rb]);
                uint32_t bh1 = *reinterpret_cast<const uint32_t*>(&sBh[rb + 8]);
                uint32_t bl0 = *reinterpret_cast<const uint32_t*>(&sBl[rb]);
                uint32_t bl1 = *reinterpret_cast<const uint32_t*>(&sBl[rb + 8]);
                MMA_BF16(acc[j][0], acc[j][1], acc[j][2], acc[j][3],
                         AH[ks][0], AH[ks][1], AH[ks][2], AH[ks][3], bh0, bh1);
                MMA_BF16(acc[j][0], acc[j][1], acc[j][2], acc[j][3],
                         AH[ks][0], AH[ks][1], AH[ks][2], AH[ks][3], bl0, bl1);
                MMA_BF16(acc[j][0], acc[j][1], acc[j][2], acc[j][3],
                         AL[ks][0], AL[ks][1], AL[ks][2], AL[ks][3], bh0, bh1);
            }
        }
        __syncthreads();   // all warps done reading buf before it's re-filled
    }

    // ---- epilogue: fragment -> g_scr (+bias) ----
    const int gy = y0 + warp;
#pragma unroll
    for (int j = 0; j < 27; j++) {
        const int oc0 = j * 8 + t * 2;
        const int oc1 = oc0 + 1;
        const float bv0 = (oc0 < NOFF) ? __ldg(off_b + oc0) : __ldg(mask_b + oc0 - NOFF);
        const float bv1 = (oc1 < NOFF) ? __ldg(off_b + oc1) : __ldg(mask_b + oc1 - NOFF);
        const int xA = x0 + g;
        const int xB = x0 + g + 8;
        g_scr[((size_t)(b * NOC + oc0) * H + gy) * W + xA] = acc[j][0] + bv0;
        g_scr[((size_t)(b * NOC + oc1) * H + gy) * W + xA] = acc[j][1] + bv1;
        g_scr[((size_t)(b * NOC + oc0) * H + gy) * W + xB] = acc[j][2] + bv0;
        g_scr[((size_t)(b * NOC + oc1) * H + gy) * W + xB] = acc[j][3] + bv1;
    }
}

// ---------------------------------------------------------------------------
// Kernel B: unchanged from R11.
// ---------------------------------------------------------------------------
#define TPX 16
#define SASTR 584

extern __shared__ __align__(16) __nv_bfloat16 smemB2[];

__global__ __launch_bounds__(128) void kernB(const float* __restrict__ bias,
                                             float* __restrict__ out)
{
    __nv_bfloat16* sAh = smemB2;
    __nv_bfloat16* sAl = smemB2 + TPX * SASTR;

    const int bx = blockIdx.x;
    const int y  = blockIdx.y;
    const int b  = blockIdx.z;
    const int x0 = bx * TPX;
    const int tid = threadIdx.x;

    const float* scr = g_scr + (size_t)b * NOC * HW;

    for (int task = tid; task < TPX * 72; task += 128) {
        int p  = task & (TPX - 1);
        int gk = task >> 4;
        int g  = gk / 9;
        int k  = gk - g * 9;
        int x  = x0 + p;
        int base = y * W + x;

        float dy = scr[(size_t)(2*gk)      * HW + base];
        float dx = scr[(size_t)(2*gk + 1)  * HW + base];
        float mr = scr[(size_t)(NOFF + gk) * HW + base];
        float m  = 1.f / (1.f + __expf(-mr));

        float ys = dy + (float)(y - 1 + k / 3);
        float xs = dx + (float)(x - 1 + k % 3);
        float yf = floorf(ys), xf = floorf(xs);
        float wy = ys - yf,    wx = xs - xf;
        int yi = (int)yf, xi = (int)xf;

        bool vy0 = (yi >= 0) && (yi < H);
        bool vy1 = (yi + 1 >= 0) && (yi + 1 < H);
        bool vx0 = (xi >= 0) && (xi < W);
        bool vx1 = (xi + 1 >= 0) && (xi + 1 < W);

        float w00 = ((vy0 && vx0) ? (1.f - wy) * (1.f - wx) : 0.f) * m;
        float w01 = ((vy0 && vx1) ? (1.f - wy) * wx         : 0.f) * m;
        float w10 = ((vy1 && vx0) ? wy * (1.f - wx)         : 0.f) * m;
        float w11 = ((vy1 && vx1) ? wy * wx                 : 0.f) * m;

        int yc0 = min(max(yi,     0), H - 1);
        int yc1 = min(max(yi + 1, 0), H - 1);
        int xc0 = min(max(xi,     0), W - 1);
        int xc1 = min(max(xi + 1, 0), W - 1);

        const float* gb = g_tr + (size_t)(b * DG + g) * HW * CG;
        const float4* t00 = reinterpret_cast<const float4*>(gb + (size_t)(yc0 * W + xc0) * CG);
        const float4* t01 = reinterpret_cast<const float4*>(gb + (size_t)(yc0 * W + xc1) * CG);
        const float4* t10 = reinterpret_cast<const float4*>(gb + (size_t)(yc1 * W + xc0) * CG);
        const float4* t11 = reinterpret_cast<const float4*>(gb + (size_t)(yc1 * W + xc1) * CG);

        float4 a00 = __ldg(t00),     b00 = __ldg(t00 + 1);
        float4 a01 = __ldg(t01),     b01 = __ldg(t01 + 1);
        float4 a10 = __ldg(t10),     b10 = __ldg(t10 + 1);
        float4 a11 = __ldg(t11),     b11 = __ldg(t11 + 1);

        float v[8];
        v[0] = w00*a00.x + w01*a01.x + w10*a10.x + w11*a11.x;
        v[1] = w00*a00.y + w01*a01.y + w10*a10.y + w11*a11.y;
        v[2] = w00*a00.z + w01*a01.z + w10*a10.z + w11*a11.z;
        v[3] = w00*a00.w + w01*a01.w + w10*a10.w + w11*a11.w;
        v[4] = w00*b00.x + w01*b01.x + w10*b10.x + w11*b11.x;
        v[5] = w00*b00.y + w01*b01.y + w10*b10.y + w11*b11.y;
        v[6] = w00*b00.z + w01*b01.z + w10*b10.z + w11*b11.z;
        v[7] = w00*b00.w + w01*b01.w + w10*b10.w + w11*b11.w;

        uint32_t hw_[4], lw_[4];
#pragma unroll
        for (int i = 0; i < 4; i++)
            split2(v[2*i], v[2*i+1], hw_[i], lw_[i]);
        const int el = p * SASTR + g * 72 + k * 8;
        *reinterpret_cast<uint4*>(&sAh[el]) = make_uint4(hw_[0], hw_[1], hw_[2], hw_[3]);
        *reinterpret_cast<uint4*>(&sAl[el]) = make_uint4(lw_[0], lw_[1], lw_[2], lw_[3]);
    }
    __syncthreads();

    const int warp = tid >> 5;
    const int lane = tid & 31;
    const int t    = lane & 3;
    const int gl   = lane >> 2;

    float acc[2][4];
#pragma unroll
    for (int jj = 0; jj < 2; jj++)
#pragma unroll
        for (int q = 0; q < 4; q++) acc[jj][q] = 0.f;

#pragma unroll 4
    for (int s = 0; s < 36; s++) {
        const int ra = gl * SASTR + s * 16 + t * 2;
        uint32_t ah0 = *reinterpret_cast<const uint32_t*>(&sAh[ra]);
        uint32_t ah1 = *reinterpret_cast<const uint32_t*>(&sAh[ra + 8 * SASTR]);
        uint32_t ah2 = *reinterpret_cast<const uint32_t*>(&sAh[ra + 8]);
        uint32_t ah3 = *reinterpret_cast<const uint32_t*>(&sAh[ra + 8 * SASTR + 8]);
        uint32_t al0 = *reinterpret_cast<const uint32_t*>(&sAl[ra]);
        uint32_t al1 = *reinterpret_cast<const uint32_t*>(&sAl[ra + 8 * SASTR]);
        uint32_t al2 = *reinterpret_cast<const uint32_t*>(&sAl[ra + 8]);
        uint32_t al3 = *reinterpret_cast<const uint32_t*>(&sAl[ra + 8 * SASTR + 8]);
#pragma unroll
        for (int jj = 0; jj < 2; jj++) {
            const int j = warp * 2 + jj;
            uint2 bh = __ldg(&g_wpan[0][j][s][lane]);
            uint2 bl = __ldg(&g_wpan[1][j][s][lane]);
            MMA_BF16(acc[jj][0], acc[jj][1], acc[jj][2], acc[jj][3],
                     ah0, ah1, ah2, ah3, bh.x, bh.y);
            MMA_BF16(acc[jj][0], acc[jj][1], acc[jj][2], acc[jj][3],
                     ah0, ah1, ah2, ah3, bl.x, bl.y);
            MMA_BF16(acc[jj][0], acc[jj][1], acc[jj][2], acc[jj][3],
                     al0, al1, al2, al3, bh.x, bh.y);
        }
    }

#pragma unroll
    for (int jj = 0; jj < 2; jj++) {
        const int j = warp * 2 + jj;
        const int oc0 = j * 8 + t * 2;
        const int oc1 = oc0 + 1;
        const float bv0 = __ldg(bias + oc0);
        const float bv1 = __ldg(bias + oc1);
        const int xA = x0 + gl;
        const int xB = x0 + gl + 8;
        out[((size_t)(b * C + oc0) * H + y) * W + xA] = acc[jj][0] + bv0;
        out[((size_t)(b * C + oc1) * H + y) * W + xA] = acc[jj][1] + bv1;
        out[((size_t)(b * C + oc0) * H + y) * W + xB] = acc[jj][2] + bv0;
        out[((size_t)(b * C + oc1) * H + y) * W + xB] = acc[jj][3] + bv1;
    }
}

// ---------------------------------------------------------------------------
extern "C" void kernel_launch(void* const* d_in, const int* in_sizes, int n_in,
                              void* d_out, int out_size) {
    const float* ref    = (const float*)d_in[0];
    const float* nbr    = (const float*)d_in[1];
    const float* off_w  = (const float*)d_in[2];
    const float* off_b  = (const float*)d_in[3];
    const float* mask_w = (const float*)d_in[4];
    const float* mask_b = (const float*)d_in[5];
    const float* weight = (const float*)d_in[6];
    const float* bias   = (const float*)d_in[7];
    float* out = (float*)d_out;

    static int attr_set = 0;
    const int kb_smem = 2 * TPX * SASTR * 2;   // 37376 B
    if (!attr_set) {
        cudaFuncSetAttribute(convA_mma, cudaFuncAttributeMaxDynamicSharedMemorySize, CMA_SMEM);
        attr_set = 1;
    }

    prepW<<<dim3(NOC, 18), 64>>>(off_w, mask_w);
    prepW2<<<dim3(8, 36), 32>>>(weight);

    dim3 gT(W / 32, H, BB);
    transp<<<gT, 256>>>(nbr);

    dim3 gC(W / 16, H / 8, BB);
    convA_mma<<<gC, 256, CMA_SMEM>>>(ref, nbr, off_b, mask_b);

    dim3 gB(W / TPX, H, BB);
    kernB<<<gB, 128, kb_smem>>>(bias, out);
}